// round 13
// baseline (speedup 1.0000x reference)
#include <cuda_runtime.h>
#include <math.h>

// Problem constants
#define BB   4
#define NN   16384
#define QK_SCALE 0.17677669529663687f   // 32^-0.5

// ---------------- scratch (device globals; no allocation) ----------------
__device__ float    g_wt[64 * 4096];         // conv weights transposed [o][k]
__device__ float    g_part[16 * 1024 * 64];  // conv split-K partials
__device__ unsigned g_ktf[8 * 256 * 32];     // K tf32 [b*2+h][m][d]
__device__ unsigned g_vhi[8 * 128 * 32];     // V bf16-hi pairs [b*2+h][k2][n]
__device__ unsigned g_vlo[8 * 128 * 32];     // V bf16-lo pairs [b*2+h][k2][n]

// ---------------- helpers ----------------
__device__ __forceinline__ unsigned f2tf(float f) {
    unsigned u; asm("cvt.rna.tf32.f32 %0, %1;" : "=r"(u) : "f"(f)); return u;
}
__device__ __forceinline__ unsigned packbf(float lo, float hi) {
    unsigned u; asm("cvt.rn.bf16x2.f32 %0, %1, %2;" : "=r"(u) : "f"(hi), "f"(lo)); return u;
}
__device__ __forceinline__ float bf_lo(unsigned u) { return __uint_as_float(u << 16); }
__device__ __forceinline__ float bf_hi(unsigned u) { return __uint_as_float(u & 0xffff0000u); }
__device__ __forceinline__ void mma8(float d[4], const unsigned a[4], const unsigned b[2]) {
    asm volatile(
        "mma.sync.aligned.m16n8k8.row.col.f32.tf32.tf32.f32 "
        "{%0,%1,%2,%3},{%4,%5,%6,%7},{%8,%9},{%0,%1,%2,%3};"
        : "+f"(d[0]), "+f"(d[1]), "+f"(d[2]), "+f"(d[3])
        : "r"(a[0]), "r"(a[1]), "r"(a[2]), "r"(a[3]), "r"(b[0]), "r"(b[1]));
}
__device__ __forceinline__ void mma16b(float d[4], const unsigned a[4], const unsigned b[2]) {
    asm volatile(
        "mma.sync.aligned.m16n8k16.row.col.f32.bf16.bf16.f32 "
        "{%0,%1,%2,%3},{%4,%5,%6,%7},{%8,%9},{%0,%1,%2,%3};"
        : "+f"(d[0]), "+f"(d[1]), "+f"(d[2]), "+f"(d[3])
        : "r"(a[0]), "r"(a[1]), "r"(a[2]), "r"(a[3]), "r"(b[0]), "r"(b[1]));
}
__device__ __forceinline__ void cpa16(unsigned dst, const void* src) {
    asm volatile("cp.async.cg.shared.global [%0], [%1], 16;" :: "r"(dst), "l"(src));
}
#define CP_COMMIT() asm volatile("cp.async.commit_group;")
#define CP_WAIT(n)  asm volatile("cp.async.wait_group %0;" :: "n"(n))

// ---------------- kernel 0: weight transpose ----------------
__global__ void __launch_bounds__(256) k_transpose(const float* __restrict__ srw) {
    int base = blockIdx.x * 256 + threadIdx.x;
#pragma unroll
    for (int it = 0; it < 4; it++) {
        int i = base + it * 65536;
        int o   = i >> 12;
        int kg  = i & 4095;
        int tap = kg >> 6, c = kg & 63;
        int kh = tap >> 3, kw = tap & 7;
        g_wt[i] = srw[((o * 64 + c) * 8 + kh) * 8 + kw];
    }
}

// ---------------- kernel 1: SR conv, cp.async double-buffered tf32 mma ----------------
__global__ void __launch_bounds__(256) k_conv(const float* __restrict__ x) {
    __shared__ float As[2][1280];   // [stage][64*20] raw fp32
    __shared__ float Bsm[2][1280];
    unsigned smbA = (unsigned)__cvta_generic_to_shared(&As[0][0]);
    unsigned smbB = (unsigned)__cvta_generic_to_shared(&Bsm[0][0]);
    int tid = threadIdx.x, w = tid >> 5, ln = tid & 31;
    int lr = ln >> 2, lc = ln & 3;
    int mtile = blockIdx.x, ks = blockIdx.y;
    int mt = w & 3, nq = w >> 2;
    float acc[4][4] = {};

    int lm = tid >> 2, lkq = tid & 3;
    int gm = mtile * 64 + lm;
    int bb = gm >> 8, pos = gm & 255;
    int oh = pos >> 4, ow = pos & 15;

    // prefetch iteration 0
    {
        int kg = ks * 256 + lkq * 4;
        int tap = kg >> 6, c = kg & 63;
        int kh = tap >> 3, kw = tap & 7;
        int pix = (oh * 8 + kh) * 128 + (ow * 8 + kw);
        cpa16(smbA + (lm * 20 + lkq * 4) * 4, &x[(bb * NN + pix) * 64 + c]);
        cpa16(smbB + (lm * 20 + lkq * 4) * 4, &g_wt[lm * 4096 + ks * 256 + lkq * 4]);
        CP_COMMIT();
    }

    for (int i = 0; i < 16; i++) {
        if (i < 15) {
            int s = (i + 1) & 1;
            int kg = ks * 256 + (i + 1) * 16 + lkq * 4;
            int tap = kg >> 6, c = kg & 63;
            int kh = tap >> 3, kw = tap & 7;
            int pix = (oh * 8 + kh) * 128 + (ow * 8 + kw);
            cpa16(smbA + (s * 1280 + lm * 20 + lkq * 4) * 4, &x[(bb * NN + pix) * 64 + c]);
            cpa16(smbB + (s * 1280 + lm * 20 + lkq * 4) * 4,
                  &g_wt[lm * 4096 + ks * 256 + (i + 1) * 16 + lkq * 4]);
            CP_COMMIT();
            CP_WAIT(1);
        } else {
            CP_WAIT(0);
        }
        __syncthreads();
        const float* Ab = As[i & 1];
        const float* Bb = Bsm[i & 1];
#pragma unroll
        for (int kb = 0; kb < 16; kb += 8) {
            const float* ap = &Ab[(mt * 16 + lr) * 20 + kb + lc];
            unsigned af[4] = {f2tf(ap[0]), f2tf(ap[8 * 20]), f2tf(ap[4]), f2tf(ap[8 * 20 + 4])};
#pragma unroll
            for (int nt = 0; nt < 4; nt++) {
                const float* bp = &Bb[(nq * 32 + nt * 8 + lr) * 20 + kb + lc];
                unsigned bf[2] = {f2tf(bp[0]), f2tf(bp[4])};
                mma8(acc[nt], af, bf);
            }
        }
        __syncthreads();
    }
    float* outp = &g_part[ks * 65536 + (mtile * 64) * 64];
#pragma unroll
    for (int nt = 0; nt < 4; nt++) {
        int r = mt * 16 + lr, c0 = nq * 32 + nt * 8 + 2 * lc;
        *(float2*)&outp[r * 64 + c0]       = make_float2(acc[nt][0], acc[nt][1]);
        *(float2*)&outp[(r + 8) * 64 + c0] = make_float2(acc[nt][2], acc[nt][3]);
    }
}

// ---------------- kernel 2: reduce partials -> LN -> kv proj -> precomputed formats ----
__global__ void __launch_bounds__(256) k_lnkv(
    const float* __restrict__ srb, const float* __restrict__ lng,
    const float* __restrict__ lnb, const float* __restrict__ kvw,
    const float* __restrict__ kvb)
{
    __shared__ float snx[2][64];
    __shared__ float red[2][2][2];
    __shared__ float vsm[2][64];
    int tid = threadIdx.x, sub = tid >> 7, t = tid & 127;
    int m = blockIdx.x * 2 + sub;
    float v = 0.f;
    if (t < 64) {
        v = srb[t];
#pragma unroll
        for (int s = 0; s < 16; s++) v += g_part[s * 65536 + m * 64 + t];
        float sv = v, sq = v * v;
#pragma unroll
        for (int off = 16; off; off >>= 1) {
            sv += __shfl_xor_sync(0xffffffffu, sv, off);
            sq += __shfl_xor_sync(0xffffffffu, sq, off);
        }
        if ((t & 31) == 0) { red[sub][t >> 5][0] = sv; red[sub][t >> 5][1] = sq; }
    }
    __syncthreads();
    float mu  = (red[sub][0][0] + red[sub][1][0]) * (1.f / 64.f);
    float var = (red[sub][0][1] + red[sub][1][1]) * (1.f / 64.f) - mu * mu;
    float rstd = rsqrtf(var + 1e-5f);
    if (t < 64) snx[sub][t] = (v - mu) * rstd * lng[t] + lnb[t];
    __syncthreads();

    int o = t;
    float acc = kvb[o];
#pragma unroll
    for (int c4 = 0; c4 < 16; c4++) {
        float4 ww = *(const float4*)&kvw[o * 64 + c4 * 4];
        acc += snx[sub][c4 * 4 + 0] * ww.x + snx[sub][c4 * 4 + 1] * ww.y
             + snx[sub][c4 * 4 + 2] * ww.z + snx[sub][c4 * 4 + 3] * ww.w;
    }
    int bb = m >> 8, mm = m & 255;
    if (o < 64) {
        int h = o >> 5, d = o & 31;
        g_ktf[((bb * 2 + h) * 256 + mm) * 32 + d] = f2tf(acc);
    } else {
        vsm[sub][o - 64] = acc;
    }
    __syncthreads();
    if (tid < 64) {
        int h = tid >> 5, d = tid & 31;
        float v0 = vsm[0][tid], v1 = vsm[1][tid];
        unsigned hi = packbf(v0, v1);
        unsigned lo = packbf(v0 - bf_lo(hi), v1 - bf_hi(hi));
        int bb2 = blockIdx.x >> 7, k2 = blockIdx.x & 127;
        int idx = ((bb2 * 2 + h) * 128 + k2) * 32 + d;
        g_vhi[idx] = hi;
        g_vlo[idx] = lo;
    }
}

// ---------------- kernel 3: fused attention, 32-row tiles, 2 CTAs/SM ----------
// smem layout (4-byte words):
#define SQ    0        // q tf32 [r*68 + h*32+d] (32 rows)              (2176)
#define SOB   2176     // attn-out tf32 [r*68+c] (32 rows)              (2176)
#define SK    4352     // qw raw @start; K tf32 [m*36+d]; pw raw @end   (9216)
#define SVH   13568    // V bf16-hi packed [k2*40 + n]                  (5120)
#define SVL   18688    // V bf16-lo packed [k2*40 + n]                  (5120)
#define SRED  23808    // x-tile raw @start; attn@V partials [nh][32][34] (4352)
#define SROW  28160    // row sums [32][4]                              (128)
#define SMFW  28288    // words -> 113152 bytes (fits 2 CTAs/SM)

__global__ void __launch_bounds__(256, 2) k_attn(
    const float* __restrict__ x,  const float* __restrict__ pos,
    const float* __restrict__ qw, const float* __restrict__ qb,
    const float* __restrict__ pw, const float* __restrict__ pb,
    const float* __restrict__ alpha, float* __restrict__ out)
{
    extern __shared__ float sm[];
    unsigned* smU = (unsigned*)sm;
    unsigned smb = (unsigned)__cvta_generic_to_shared(sm);
    int tid = threadIdx.x, w = tid >> 5, ln = tid & 31;
    int lr = ln >> 2, lc = ln & 3;
    int b = blockIdx.y;
    int n0 = blockIdx.x * 32;
    float a_ = __ldg(alpha);

    int mt = w & 1, nh = w >> 1;            // logits/attn decomposition (8 warps)
    int rowA = mt * 16 + lr;                // 0..31

    // ---- G0: x tile raw -> SRED, qw raw -> SK, V0 -> SVH/SVL ----
#pragma unroll
    for (int it = 0; it < 2; it++) {
        int lin = it * 256 + tid;               // 512 uint4
        int r = lin >> 4, c4 = (lin & 15) * 4;
        cpa16(smb + (SRED + r * 68 + c4) * 4, &x[((size_t)b * NN + n0 + r) * 64 + c4]);
    }
#pragma unroll
    for (int it = 0; it < 4; it++) {
        int lin = it * 256 + tid;               // 1024 uint4
        int r = lin >> 4, c4 = (lin & 15) * 4;
        cpa16(smb + (SK + r * 68 + c4) * 4, &qw[r * 64 + c4]);
    }
    {
        int b2h = b * 2;
#pragma unroll
        for (int it = 0; it < 4; it++) {
            int lin = it * 256 + tid;           // 1024 uint4 per plane
            int k2 = lin >> 3, n4 = (lin & 7) * 4;
            cpa16(smb + (SVH + k2 * 40 + n4) * 4, &g_vhi[(b2h * 128 + k2) * 32 + n4]);
            cpa16(smb + (SVL + k2 * 40 + n4) * 4, &g_vlo[(b2h * 128 + k2) * 32 + n4]);
        }
    }
    CP_COMMIT();
    CP_WAIT(0);
    __syncthreads();     // B1: x, qw, V0 staged

    // ---- q-proj: SQ[32,64] = x @ qw^T (cvt at use, scale folded) ----
    {
        int mtp = w & 1, nq = w >> 1;
        float acc[2][4] = {};
#pragma unroll
        for (int ks = 0; ks < 8; ks++) {
            const float* ap = &sm[SRED + (mtp * 16 + lr) * 68 + ks * 8 + lc];
            unsigned af[4] = {f2tf(ap[0]), f2tf(ap[8 * 68]), f2tf(ap[4]), f2tf(ap[8 * 68 + 4])};
#pragma unroll
            for (int nt = 0; nt < 2; nt++) {
                const float* bp = &sm[SK + (nq * 16 + nt * 8 + lr) * 68 + ks * 8 + lc];
                unsigned bf[2] = {f2tf(bp[0]), f2tf(bp[4])};
                mma8(acc[nt], af, bf);
            }
        }
#pragma unroll
        for (int nt = 0; nt < 2; nt++) {
            int c0 = nq * 16 + nt * 8 + 2 * lc;
            int r = mtp * 16 + lr;
            float b0 = __ldg(&qb[c0]), b1 = __ldg(&qb[c0 + 1]);
            smU[SQ + r * 68 + c0]           = f2tf((acc[nt][0] + b0) * QK_SCALE);
            smU[SQ + r * 68 + c0 + 1]       = f2tf((acc[nt][1] + b1) * QK_SCALE);
            smU[SQ + (r + 8) * 68 + c0]     = f2tf((acc[nt][2] + b0) * QK_SCALE);
            smU[SQ + (r + 8) * 68 + c0 + 1] = f2tf((acc[nt][3] + b1) * QK_SCALE);
        }
    }
    __syncthreads();     // B2: qw reads done -> SK reusable

    // ---- G1: K0 -> SK (exposed once; co-resident CTA hides) ----
#pragma unroll
    for (int it = 0; it < 8; it++) {
        int lin = it * 256 + tid;               // 2048 uint4
        int m = lin >> 3, d4 = (lin & 7) * 4;
        cpa16(smb + (SK + m * 36 + d4) * 4, &g_ktf[(b * 2 * 256 + m) * 32 + d4]);
    }
    CP_COMMIT();
    CP_WAIT(0);
    __syncthreads();     // B3: K0 staged

    for (int h = 0; h < 2; h++) {
        int b2h = b * 2 + h;

        // ---- logits rows [mt*16..+15], cols [nh*64..+63] (registers) ----
        float acc[8][4];
#pragma unroll
        for (int i = 0; i < 8; i++)
            acc[i][0] = acc[i][1] = acc[i][2] = acc[i][3] = 0.f;
#pragma unroll
        for (int ks = 0; ks < 4; ks++) {
            const unsigned* ab = &smU[SQ + rowA * 68 + h * 32 + ks * 8 + lc];
            unsigned af[4] = {ab[0], ab[8 * 68], ab[4], ab[8 * 68 + 4]};
#pragma unroll
            for (int nt = 0; nt < 8; nt++) {
                const unsigned* bp = &smU[SK + (nh * 64 + nt * 8 + lr) * 36 + ks * 8 + lc];
                unsigned bf[2] = {bp[0], bp[4]};
                mma8(acc[nt], af, bf);
            }
        }

        // ---- exp (logits O(1): no max pass) + row-sum exchange ----
        float s0 = 0.f, s1 = 0.f;
#pragma unroll
        for (int nt = 0; nt < 8; nt++) {
            acc[nt][0] = __expf(acc[nt][0]); s0 += acc[nt][0];
            acc[nt][1] = __expf(acc[nt][1]); s0 += acc[nt][1];
            acc[nt][2] = __expf(acc[nt][2]); s1 += acc[nt][2];
            acc[nt][3] = __expf(acc[nt][3]); s1 += acc[nt][3];
        }
        s0 += __shfl_xor_sync(0xffffffffu, s0, 1);
        s0 += __shfl_xor_sync(0xffffffffu, s0, 2);
        s1 += __shfl_xor_sync(0xffffffffu, s1, 1);
        s1 += __shfl_xor_sync(0xffffffffu, s1, 2);
        if (lc == 0) {
            sm[SROW + rowA * 4 + nh]       = s0;
            sm[SROW + (rowA + 8) * 4 + nh] = s1;
        }
        __syncthreads();   // B4: sums visible; all SK logits reads done

        if (h == 0) {      // G2: K1 -> SK (overlaps blend+attn@V+reduce)
#pragma unroll
            for (int it = 0; it < 8; it++) {
                int lin = it * 256 + tid;
                int m = lin >> 3, d4 = (lin & 7) * 4;
                cpa16(smb + (SK + m * 36 + d4) * 4,
                      &g_ktf[((b2h + 1) * 256 + m) * 32 + d4]);
            }
            CP_COMMIT();
        }

        float4 s40 = *(float4*)&sm[SROW + rowA * 4];
        float4 s41 = *(float4*)&sm[SROW + (rowA + 8) * 4];
        float inv0 = (1.f - a_) / (s40.x + s40.y + s40.z + s40.w);
        float inv1 = (1.f - a_) / (s41.x + s41.y + s41.z + s41.w);

        // ---- blend (pos via LDG; co-CTA hides) + split-bf16 + attn@V partial ----
        const float* pr0 = &pos[((size_t)b2h * NN + n0 + rowA) * 256];
        const float* pr1 = pr0 + 8 * 256;
        float accO[4][4];
#pragma unroll
        for (int i = 0; i < 4; i++)
            accO[i][0] = accO[i][1] = accO[i][2] = accO[i][3] = 0.f;
#pragma unroll
        for (int kk = 0; kk < 4; kk++) {
            unsigned afh[4], afl[4];
#pragma unroll
            for (int q = 0; q < 2; q++) {
                int nt = 2 * kk + q;
                int cb = nh * 64 + nt * 8 + 2 * lc;
                float2 p0 = __ldg((const float2*)&pr0[cb]);
                float2 p1 = __ldg((const float2*)&pr1[cb]);
                float w00 = acc[nt][0] * inv0 + a_ * p0.x;
                float w01 = acc[nt][1] * inv0 + a_ * p0.y;
                float w10 = acc[nt][2] * inv1 + a_ * p1.x;
                float w11 = acc[nt][3] * inv1 + a_ * p1.y;
                unsigned h0 = packbf(w00, w01);
                unsigned h1 = packbf(w10, w11);
                afh[2 * q]     = h0;
                afh[2 * q + 1] = h1;
                afl[2 * q]     = packbf(w00 - bf_lo(h0), w01 - bf_hi(h0));
                afl[2 * q + 1] = packbf(w10 - bf_lo(h1), w11 - bf_hi(h1));
            }
            int k2b = nh * 32 + kk * 8;
#pragma unroll
            for (int ntv = 0; ntv < 4; ntv++) {
                const unsigned* bph = &smU[SVH + (k2b + lc) * 40 + ntv * 8 + lr];
                const unsigned* bpl = &smU[SVL + (k2b + lc) * 40 + ntv * 8 + lr];
                unsigned bh[2] = {bph[0], bph[4 * 40]};
                unsigned bl[2] = {bpl[0], bpl[4 * 40]};
                mma16b(accO[ntv], afh, bh);
                mma16b(accO[ntv], afh, bl);
                mma16b(accO[ntv], afl, bh);
            }
        }

        // write partials [nh][32][34]
#pragma unroll
        for (int ntv = 0; ntv < 4; ntv++) {
            int cc = ntv * 8 + 2 * lc;
            *(float2*)&sm[SRED + nh * 1088 + rowA * 34 + cc] =
                make_float2(accO[ntv][0], accO[ntv][1]);
            *(float2*)&sm[SRED + nh * 1088 + (rowA + 8) * 34 + cc] =
                make_float2(accO[ntv][2], accO[ntv][3]);
        }
        __syncthreads();   // B5: partials visible; all SVH/SVL reads done

        if (h == 0) {      // G3: V1 -> SVH/SVL (overlaps reduce)
#pragma unroll
            for (int it = 0; it < 4; it++) {
                int lin = it * 256 + tid;
                int k2 = lin >> 3, n4 = (lin & 7) * 4;
                cpa16(smb + (SVH + k2 * 40 + n4) * 4,
                      &g_vhi[((b2h + 1) * 128 + k2) * 32 + n4]);
                cpa16(smb + (SVL + k2 * 40 + n4) * 4,
                      &g_vlo[((b2h + 1) * 128 + k2) * 32 + n4]);
            }
            CP_COMMIT();
        } else {           // G4: pw raw -> SK (all K reads done)
#pragma unroll
            for (int it = 0; it < 4; it++) {
                int lin = it * 256 + tid;
                int r = lin >> 4, c4 = (lin & 15) * 4;
                cpa16(smb + (SK + r * 68 + c4) * 4, &pw[r * 64 + c4]);
            }
            CP_COMMIT();
        }

        // ---- reduce 4 partials -> SOB (tf32) ----
#pragma unroll
        for (int i = 0; i < 2; i++) {
            int p = i * 256 + tid;        // 512 col-pairs
            int r = p >> 4, c2 = (p & 15) * 2;
            float sx = 0.f, sy = 0.f;
#pragma unroll
            for (int g = 0; g < 4; g++) {
                float2 t = *(float2*)&sm[SRED + g * 1088 + r * 34 + c2];
                sx += t.x; sy += t.y;
            }
            smU[SOB + r * 68 + h * 32 + c2]     = f2tf(sx);
            smU[SOB + r * 68 + h * 32 + c2 + 1] = f2tf(sy);
        }
        CP_WAIT(0);        // drain (h0: K1+V1, h1: pw)
        __syncthreads();   // B6
    }

    // ---- out-proj: out = attn_out @ pw^T + pb (pw raw, cvt at use) ----
    {
        int mtp = w & 1, nq = w >> 1;
        float acc[2][4] = {};
#pragma unroll
        for (int ks = 0; ks < 8; ks++) {
            const unsigned* ab = &smU[SOB + (mtp * 16 + lr) * 68 + ks * 8 + lc];
            unsigned af[4] = {ab[0], ab[8 * 68], ab[4], ab[8 * 68 + 4]};
#pragma unroll
            for (int nt = 0; nt < 2; nt++) {
                const float* bp = &sm[SK + (nq * 16 + nt * 8 + lr) * 68 + ks * 8 + lc];
                unsigned bf[2] = {f2tf(bp[0]), f2tf(bp[4])};
                mma8(acc[nt], af, bf);
            }
        }
#pragma unroll
        for (int nt = 0; nt < 2; nt++) {
            int c0 = nq * 16 + nt * 8 + 2 * lc;
            int r = mtp * 16 + lr;
            float b0 = __ldg(&pb[c0]), b1 = __ldg(&pb[c0 + 1]);
            *(float2*)&out[((size_t)b * NN + n0 + r) * 64 + c0] =
                make_float2(acc[nt][0] + b0, acc[nt][1] + b1);
            *(float2*)&out[((size_t)b * NN + n0 + r + 8) * 64 + c0] =
                make_float2(acc[nt][2] + b0, acc[nt][3] + b1);
        }
    }
}

// ---------------- launch ----------------
extern "C" void kernel_launch(void* const* d_in, const int* in_sizes, int n_in,
                              void* d_out, int out_size) {
    const float* x     = (const float*)d_in[0];
    const float* pos   = (const float*)d_in[1];
    const float* qw    = (const float*)d_in[2];
    const float* qb    = (const float*)d_in[3];
    const float* kvw   = (const float*)d_in[4];
    const float* kvb   = (const float*)d_in[5];
    const float* pw    = (const float*)d_in[6];
    const float* pb    = (const float*)d_in[7];
    const float* srw   = (const float*)d_in[8];
    const float* srb   = (const float*)d_in[9];
    const float* lng   = (const float*)d_in[10];
    const float* lnb   = (const float*)d_in[11];
    const float* alpha = (const float*)d_in[12];
    float* out = (float*)d_out;

    cudaFuncSetAttribute(k_attn, cudaFuncAttributeMaxDynamicSharedMemorySize,
                         SMFW * 4);

    k_transpose<<<256, 256>>>(srw);
    k_conv<<<dim3(16, 16), 256>>>(x);
    k_lnkv<<<512, 256>>>(srb, lng, lnb, kvw, kvb);
    k_attn<<<dim3(512, 4), 256, SMFW * 4>>>(x, pos, qw, qb, pw, pb, alpha, out);
}

// round 14
// speedup vs baseline: 1.0737x; 1.0737x over previous
#include <cuda_runtime.h>
#include <math.h>

// Problem constants
#define BB   4
#define NN   16384
#define QK_SCALE 0.17677669529663687f   // 32^-0.5

// ---------------- scratch (device globals; no allocation) ----------------
__device__ float    g_wt[64 * 4096];         // conv weights transposed [o][k]
__device__ float    g_part[32 * 1024 * 64];  // conv split-K partials (32 splits)
__device__ unsigned g_ktf[8 * 256 * 32];     // K tf32 [b*2+h][m][d]
__device__ unsigned g_vhi[8 * 128 * 32];     // V bf16-hi pairs [b*2+h][k2][n]
__device__ unsigned g_vlo[8 * 128 * 32];     // V bf16-lo pairs [b*2+h][k2][n]

// ---------------- helpers ----------------
__device__ __forceinline__ unsigned f2tf(float f) {
    unsigned u; asm("cvt.rna.tf32.f32 %0, %1;" : "=r"(u) : "f"(f)); return u;
}
__device__ __forceinline__ unsigned packbf(float lo, float hi) {
    unsigned u; asm("cvt.rn.bf16x2.f32 %0, %1, %2;" : "=r"(u) : "f"(hi), "f"(lo)); return u;
}
__device__ __forceinline__ float bf_lo(unsigned u) { return __uint_as_float(u << 16); }
__device__ __forceinline__ float bf_hi(unsigned u) { return __uint_as_float(u & 0xffff0000u); }
__device__ __forceinline__ void mma8(float d[4], const unsigned a[4], const unsigned b[2]) {
    asm volatile(
        "mma.sync.aligned.m16n8k8.row.col.f32.tf32.tf32.f32 "
        "{%0,%1,%2,%3},{%4,%5,%6,%7},{%8,%9},{%0,%1,%2,%3};"
        : "+f"(d[0]), "+f"(d[1]), "+f"(d[2]), "+f"(d[3])
        : "r"(a[0]), "r"(a[1]), "r"(a[2]), "r"(a[3]), "r"(b[0]), "r"(b[1]));
}
__device__ __forceinline__ void mma16b(float d[4], const unsigned a[4], const unsigned b[2]) {
    asm volatile(
        "mma.sync.aligned.m16n8k16.row.col.f32.bf16.bf16.f32 "
        "{%0,%1,%2,%3},{%4,%5,%6,%7},{%8,%9},{%0,%1,%2,%3};"
        : "+f"(d[0]), "+f"(d[1]), "+f"(d[2]), "+f"(d[3])
        : "r"(a[0]), "r"(a[1]), "r"(a[2]), "r"(a[3]), "r"(b[0]), "r"(b[1]));
}
__device__ __forceinline__ void cpa16(unsigned dst, const void* src) {
    asm volatile("cp.async.cg.shared.global [%0], [%1], 16;" :: "r"(dst), "l"(src));
}
#define CP_COMMIT() asm volatile("cp.async.commit_group;")
#define CP_WAIT(n)  asm volatile("cp.async.wait_group %0;" :: "n"(n))
#define GROUP_BAR(id) asm volatile("bar.sync %0, 128;" :: "r"(id) : "memory")

// ---------------- kernel 0: weight transpose ----------------
__global__ void __launch_bounds__(256) k_transpose(const float* __restrict__ srw) {
    int base = blockIdx.x * 256 + threadIdx.x;
#pragma unroll
    for (int it = 0; it < 4; it++) {
        int i = base + it * 65536;
        int o   = i >> 12;
        int kg  = i & 4095;
        int tap = kg >> 6, c = kg & 63;
        int kh = tap >> 3, kw = tap & 7;
        g_wt[i] = srw[((o * 64 + c) * 8 + kh) * 8 + kw];
    }
}

// ---------------- kernel 1: SR conv, split-K 32, cp.async double-buffered tf32 mma ----
__global__ void __launch_bounds__(256) k_conv(const float* __restrict__ x) {
    __shared__ float As[2][1280];   // [stage][64*20] raw fp32
    __shared__ float Bsm[2][1280];
    unsigned smbA = (unsigned)__cvta_generic_to_shared(&As[0][0]);
    unsigned smbB = (unsigned)__cvta_generic_to_shared(&Bsm[0][0]);
    int tid = threadIdx.x, w = tid >> 5, ln = tid & 31;
    int lr = ln >> 2, lc = ln & 3;
    int mtile = blockIdx.x, ks = blockIdx.y;
    int mt = w & 3, nq = w >> 2;
    float acc[4][4] = {};

    int lm = tid >> 2, lkq = tid & 3;
    int gm = mtile * 64 + lm;
    int bb = gm >> 8, pos = gm & 255;
    int oh = pos >> 4, ow = pos & 15;

    // prefetch iteration 0
    {
        int kg = ks * 128 + lkq * 4;
        int tap = kg >> 6, c = kg & 63;
        int kh = tap >> 3, kw = tap & 7;
        int pix = (oh * 8 + kh) * 128 + (ow * 8 + kw);
        cpa16(smbA + (lm * 20 + lkq * 4) * 4, &x[(bb * NN + pix) * 64 + c]);
        cpa16(smbB + (lm * 20 + lkq * 4) * 4, &g_wt[lm * 4096 + ks * 128 + lkq * 4]);
        CP_COMMIT();
    }

    for (int i = 0; i < 8; i++) {
        if (i < 7) {
            int s = (i + 1) & 1;
            int kg = ks * 128 + (i + 1) * 16 + lkq * 4;
            int tap = kg >> 6, c = kg & 63;
            int kh = tap >> 3, kw = tap & 7;
            int pix = (oh * 8 + kh) * 128 + (ow * 8 + kw);
            cpa16(smbA + (s * 1280 + lm * 20 + lkq * 4) * 4, &x[(bb * NN + pix) * 64 + c]);
            cpa16(smbB + (s * 1280 + lm * 20 + lkq * 4) * 4,
                  &g_wt[lm * 4096 + ks * 128 + (i + 1) * 16 + lkq * 4]);
            CP_COMMIT();
            CP_WAIT(1);
        } else {
            CP_WAIT(0);
        }
        __syncthreads();
        const float* Ab = As[i & 1];
        const float* Bb = Bsm[i & 1];
#pragma unroll
        for (int kb = 0; kb < 16; kb += 8) {
            const float* ap = &Ab[(mt * 16 + lr) * 20 + kb + lc];
            unsigned af[4] = {f2tf(ap[0]), f2tf(ap[8 * 20]), f2tf(ap[4]), f2tf(ap[8 * 20 + 4])};
#pragma unroll
            for (int nt = 0; nt < 4; nt++) {
                const float* bp = &Bb[(nq * 32 + nt * 8 + lr) * 20 + kb + lc];
                unsigned bf[2] = {f2tf(bp[0]), f2tf(bp[4])};
                mma8(acc[nt], af, bf);
            }
        }
        __syncthreads();
    }
    float* outp = &g_part[ks * 65536 + (mtile * 64) * 64];
#pragma unroll
    for (int nt = 0; nt < 4; nt++) {
        int r = mt * 16 + lr, c0 = nq * 32 + nt * 8 + 2 * lc;
        *(float2*)&outp[r * 64 + c0]       = make_float2(acc[nt][0], acc[nt][1]);
        *(float2*)&outp[(r + 8) * 64 + c0] = make_float2(acc[nt][2], acc[nt][3]);
    }
}

// ---------------- kernel 2: reduce partials -> LN -> kv proj -> precomputed formats ----
__global__ void __launch_bounds__(256) k_lnkv(
    const float* __restrict__ srb, const float* __restrict__ lng,
    const float* __restrict__ lnb, const float* __restrict__ kvw,
    const float* __restrict__ kvb)
{
    __shared__ float snx[2][64];
    __shared__ float red[2][2][2];
    __shared__ float vsm[2][64];
    int tid = threadIdx.x, sub = tid >> 7, t = tid & 127;
    int m = blockIdx.x * 2 + sub;
    float v = 0.f;
    if (t < 64) {
        v = srb[t];
#pragma unroll
        for (int s = 0; s < 32; s++) v += g_part[s * 65536 + m * 64 + t];
        float sv = v, sq = v * v;
#pragma unroll
        for (int off = 16; off; off >>= 1) {
            sv += __shfl_xor_sync(0xffffffffu, sv, off);
            sq += __shfl_xor_sync(0xffffffffu, sq, off);
        }
        if ((t & 31) == 0) { red[sub][t >> 5][0] = sv; red[sub][t >> 5][1] = sq; }
    }
    __syncthreads();
    float mu  = (red[sub][0][0] + red[sub][1][0]) * (1.f / 64.f);
    float var = (red[sub][0][1] + red[sub][1][1]) * (1.f / 64.f) - mu * mu;
    float rstd = rsqrtf(var + 1e-5f);
    if (t < 64) snx[sub][t] = (v - mu) * rstd * lng[t] + lnb[t];
    __syncthreads();

    int o = t;
    float acc = kvb[o];
#pragma unroll
    for (int c4 = 0; c4 < 16; c4++) {
        float4 ww = *(const float4*)&kvw[o * 64 + c4 * 4];
        acc += snx[sub][c4 * 4 + 0] * ww.x + snx[sub][c4 * 4 + 1] * ww.y
             + snx[sub][c4 * 4 + 2] * ww.z + snx[sub][c4 * 4 + 3] * ww.w;
    }
    int bb = m >> 8, mm = m & 255;
    if (o < 64) {
        int h = o >> 5, d = o & 31;
        g_ktf[((bb * 2 + h) * 256 + mm) * 32 + d] = f2tf(acc);
    } else {
        vsm[sub][o - 64] = acc;
    }
    __syncthreads();
    if (tid < 64) {
        int h = tid >> 5, d = tid & 31;
        float v0 = vsm[0][tid], v1 = vsm[1][tid];
        unsigned hi = packbf(v0, v1);
        unsigned lo = packbf(v0 - bf_lo(hi), v1 - bf_hi(hi));
        int bb2 = blockIdx.x >> 7, k2 = blockIdx.x & 127;
        int idx = ((bb2 * 2 + h) * 128 + k2) * 32 + d;
        g_vhi[idx] = hi;
        g_vlo[idx] = lo;
    }
}

// ---------------- kernel 3: fused attention (R11 champion, unchanged) ----------
// smem layout (4-byte words):
#define SQ    0        // q tf32 [r*68 + h*32+d], scale folded          (4352)
#define SOB   4352     // qw raw at start; attn-out tf32 [r*68+c]       (4352)
#define SK    8704     // K tf32 head [m*36+d]; pw raw [o*68+c] at end  (9216)
#define SVH   17920    // V bf16-hi packed [k2*40 + n]                  (5120)
#define SVL   23040    // V bf16-lo packed [k2*40 + n]                  (5120)
#define SRED  28160    // x-tile raw at start; attn@V partials [nh][64][34] (8704)
#define SROW  36864    // row sums [64][4]                              (256)
#define SPOS  37120    // pos tile f32 [64][260]                        (16640)
#define SMFW  53760    // words -> 215040 bytes

__global__ void __launch_bounds__(512, 1) k_attn(
    const float* __restrict__ x,  const float* __restrict__ pos,
    const float* __restrict__ qw, const float* __restrict__ qb,
    const float* __restrict__ pw, const float* __restrict__ pb,
    const float* __restrict__ alpha, float* __restrict__ out)
{
    extern __shared__ float sm[];
    unsigned* smU = (unsigned*)sm;
    unsigned smb = (unsigned)__cvta_generic_to_shared(sm);
    int tid = threadIdx.x, w = tid >> 5, ln = tid & 31;
    int lr = ln >> 2, lc = ln & 3;
    int b = blockIdx.y;
    int n0 = blockIdx.x * 64;
    float a_ = __ldg(alpha);

    int mt = w & 3, nh = w >> 2;            // logits/attn decomposition
    int rowA = mt * 16 + lr;

    // ---- G0: x tile raw -> SRED, qw raw -> SOB ----
#pragma unroll
    for (int it = 0; it < 2; it++) {
        int lin = it * 512 + tid;
        int r = lin >> 4, c4 = (lin & 15) * 4;
        cpa16(smb + (SRED + r * 68 + c4) * 4, &x[((size_t)b * NN + n0 + r) * 64 + c4]);
        cpa16(smb + (SOB + r * 68 + c4) * 4, &qw[r * 64 + c4]);
    }
    CP_COMMIT();
    // ---- G1: K0 + V0 ----
    {
        int b2h = b * 2;
#pragma unroll
        for (int it = 0; it < 4; it++) {
            int lin = it * 512 + tid;
            int m = lin >> 3, d4 = (lin & 7) * 4;
            cpa16(smb + (SK + m * 36 + d4) * 4, &g_ktf[(b2h * 256 + m) * 32 + d4]);
        }
#pragma unroll
        for (int it = 0; it < 2; it++) {
            int lin = it * 512 + tid;
            int k2 = lin >> 3, n4 = (lin & 7) * 4;
            cpa16(smb + (SVH + k2 * 40 + n4) * 4, &g_vhi[(b2h * 128 + k2) * 32 + n4]);
            cpa16(smb + (SVL + k2 * 40 + n4) * 4, &g_vlo[(b2h * 128 + k2) * 32 + n4]);
        }
        CP_COMMIT();
    }
    // ---- G2: pos0 slice (warp-private 16x64) ----
    {
        int b2h = b * 2;
#pragma unroll
        for (int i = 0; i < 8; i++) {
            int q = ln + 32 * i;
            int r = q >> 4, ch = q & 15;
            cpa16(smb + (SPOS + (mt * 16 + r) * 260 + nh * 64 + ch * 4) * 4,
                  &pos[((size_t)b2h * NN + n0 + mt * 16 + r) * 256 + nh * 64 + ch * 4]);
        }
        CP_COMMIT();
    }

    CP_WAIT(2);          // G0 complete (G1,G2 pending)
    __syncthreads();     // B1

    // ---- q-proj: SQ = x @ qw^T (cvt at use, scale folded) ----
    {
        int mtp = w >> 2, nq = w & 3;
        float acc[2][4] = {};
#pragma unroll
        for (int ks = 0; ks < 8; ks++) {
            const float* ap = &sm[SRED + (mtp * 16 + lr) * 68 + ks * 8 + lc];
            unsigned af[4] = {f2tf(ap[0]), f2tf(ap[8 * 68]), f2tf(ap[4]), f2tf(ap[8 * 68 + 4])};
#pragma unroll
            for (int nt = 0; nt < 2; nt++) {
                const float* bp = &sm[SOB + (nq * 16 + nt * 8 + lr) * 68 + ks * 8 + lc];
                unsigned bf[2] = {f2tf(bp[0]), f2tf(bp[4])};
                mma8(acc[nt], af, bf);
            }
        }
#pragma unroll
        for (int nt = 0; nt < 2; nt++) {
            int c0 = nq * 16 + nt * 8 + 2 * lc;
            int r = mtp * 16 + lr;
            float b0 = __ldg(&qb[c0]), b1 = __ldg(&qb[c0 + 1]);
            smU[SQ + r * 68 + c0]           = f2tf((acc[nt][0] + b0) * QK_SCALE);
            smU[SQ + r * 68 + c0 + 1]       = f2tf((acc[nt][1] + b1) * QK_SCALE);
            smU[SQ + (r + 8) * 68 + c0]     = f2tf((acc[nt][2] + b0) * QK_SCALE);
            smU[SQ + (r + 8) * 68 + c0 + 1] = f2tf((acc[nt][3] + b1) * QK_SCALE);
        }
    }
    CP_WAIT(1);          // G1 (K0/V0) complete (G2 pending)
    __syncthreads();     // B2

    for (int h = 0; h < 2; h++) {
        int b2h = b * 2 + h;

        // ---- logits rows [mt*16..+15], cols [nh*64..+63] (registers) ----
        float acc[8][4];
#pragma unroll
        for (int i = 0; i < 8; i++)
            acc[i][0] = acc[i][1] = acc[i][2] = acc[i][3] = 0.f;
#pragma unroll
        for (int ks = 0; ks < 4; ks++) {
            const unsigned* ab = &smU[SQ + rowA * 68 + h * 32 + ks * 8 + lc];
            unsigned af[4] = {ab[0], ab[8 * 68], ab[4], ab[8 * 68 + 4]};
#pragma unroll
            for (int nt = 0; nt < 8; nt++) {
                const unsigned* bp = &smU[SK + (nh * 64 + nt * 8 + lr) * 36 + ks * 8 + lc];
                unsigned bf[2] = {bp[0], bp[4]};
                mma8(acc[nt], af, bf);
            }
        }

        // ---- exp + row sums; exchange within mt-group only ----
        float s0 = 0.f, s1 = 0.f;
#pragma unroll
        for (int nt = 0; nt < 8; nt++) {
            acc[nt][0] = __expf(acc[nt][0]); s0 += acc[nt][0];
            acc[nt][1] = __expf(acc[nt][1]); s0 += acc[nt][1];
            acc[nt][2] = __expf(acc[nt][2]); s1 += acc[nt][2];
            acc[nt][3] = __expf(acc[nt][3]); s1 += acc[nt][3];
        }
        s0 += __shfl_xor_sync(0xffffffffu, s0, 1);
        s0 += __shfl_xor_sync(0xffffffffu, s0, 2);
        s1 += __shfl_xor_sync(0xffffffffu, s1, 1);
        s1 += __shfl_xor_sync(0xffffffffu, s1, 2);
        if (lc == 0) {
            sm[SROW + rowA * 4 + nh]       = s0;
            sm[SROW + (rowA + 8) * 4 + nh] = s1;
        }
        GROUP_BAR(mt + 1);     // only the 4 warps sharing mt need the sums

        float4 s40 = *(float4*)&sm[SROW + rowA * 4];
        float4 s41 = *(float4*)&sm[SROW + (rowA + 8) * 4];
        float inv0 = (1.f - a_) / (s40.x + s40.y + s40.z + s40.w);
        float inv1 = (1.f - a_) / (s41.x + s41.y + s41.z + s41.w);

        if (h == 0) {          // pos0 (G2) — warp-local wait
            CP_WAIT(0);
            __syncwarp();
        }

        // ---- blend (pos from smem) + split-bf16 pack + attn@V partial ----
        float accO[4][4];
#pragma unroll
        for (int i = 0; i < 4; i++)
            accO[i][0] = accO[i][1] = accO[i][2] = accO[i][3] = 0.f;
#pragma unroll
        for (int kk = 0; kk < 4; kk++) {
            unsigned afh[4], afl[4];
#pragma unroll
            for (int q = 0; q < 2; q++) {
                int nt = 2 * kk + q;
                int cb = nh * 64 + nt * 8 + 2 * lc;
                float2 p0 = *(const float2*)&sm[SPOS + rowA * 260 + cb];
                float2 p1 = *(const float2*)&sm[SPOS + (rowA + 8) * 260 + cb];
                float w00 = acc[nt][0] * inv0 + a_ * p0.x;
                float w01 = acc[nt][1] * inv0 + a_ * p0.y;
                float w10 = acc[nt][2] * inv1 + a_ * p1.x;
                float w11 = acc[nt][3] * inv1 + a_ * p1.y;
                unsigned h0 = packbf(w00, w01);
                unsigned h1 = packbf(w10, w11);
                afh[2 * q]     = h0;
                afh[2 * q + 1] = h1;
                afl[2 * q]     = packbf(w00 - bf_lo(h0), w01 - bf_hi(h0));
                afl[2 * q + 1] = packbf(w10 - bf_lo(h1), w11 - bf_hi(h1));
            }
            int k2b = nh * 32 + kk * 8;
#pragma unroll
            for (int ntv = 0; ntv < 4; ntv++) {
                const unsigned* bph = &smU[SVH + (k2b + lc) * 40 + ntv * 8 + lr];
                const unsigned* bpl = &smU[SVL + (k2b + lc) * 40 + ntv * 8 + lr];
                unsigned bh[2] = {bph[0], bph[4 * 40]};
                unsigned bl[2] = {bpl[0], bpl[4 * 40]};
                mma16b(accO[ntv], afh, bh);
                mma16b(accO[ntv], afh, bl);
                mma16b(accO[ntv], afl, bh);
            }
        }

        if (h == 0) {          // G4: pos1 slice (own slice read done; warp-private)
#pragma unroll
            for (int i = 0; i < 8; i++) {
                int q = ln + 32 * i;
                int r = q >> 4, ch = q & 15;
                cpa16(smb + (SPOS + (mt * 16 + r) * 260 + nh * 64 + ch * 4) * 4,
                      &pos[((size_t)(b2h + 1) * NN + n0 + mt * 16 + r) * 256 + nh * 64 + ch * 4]);
            }
            CP_COMMIT();
        }

        // write partials [nh][row][col]
#pragma unroll
        for (int ntv = 0; ntv < 4; ntv++) {
            int cc = ntv * 8 + 2 * lc;
            *(float2*)&sm[SRED + nh * 2176 + rowA * 34 + cc] =
                make_float2(accO[ntv][0], accO[ntv][1]);
            *(float2*)&sm[SRED + nh * 2176 + (rowA + 8) * 34 + cc] =
                make_float2(accO[ntv][2], accO[ntv][3]);
        }
        __syncthreads();       // B3 full: partials visible; all SK/SV reads done

        if (h == 0) {          // G35: K1 + V1 (after ALL logits/attn@V reads)
#pragma unroll
            for (int it = 0; it < 4; it++) {
                int lin = it * 512 + tid;
                int m = lin >> 3, d4 = (lin & 7) * 4;
                cpa16(smb + (SK + m * 36 + d4) * 4,
                      &g_ktf[((b2h + 1) * 256 + m) * 32 + d4]);
            }
#pragma unroll
            for (int it = 0; it < 2; it++) {
                int lin = it * 512 + tid;
                int k2 = lin >> 3, n4 = (lin & 7) * 4;
                cpa16(smb + (SVH + k2 * 40 + n4) * 4,
                      &g_vhi[((b2h + 1) * 128 + k2) * 32 + n4]);
                cpa16(smb + (SVL + k2 * 40 + n4) * 4,
                      &g_vlo[((b2h + 1) * 128 + k2) * 32 + n4]);
            }
            CP_COMMIT();
        } else {               // G6: pw raw -> SK (K reads all done)
#pragma unroll
            for (int it = 0; it < 2; it++) {
                int lin = it * 512 + tid;
                int r = lin >> 4, c4 = (lin & 15) * 4;
                cpa16(smb + (SK + r * 68 + c4) * 4, &pw[r * 64 + c4]);
            }
            CP_COMMIT();
        }

        // ---- reduce own-group rows: partials -> SOB (tf32) ----
        {
            int tg = (w >> 2) * 32 + ln;      // 0..127 within mt-group
#pragma unroll
            for (int i = 0; i < 2; i++) {
                int p = i * 128 + tg;         // 0..255
                int r = mt * 16 + (p >> 4);
                int c2 = (p & 15) * 2;
                float sx = 0.f, sy = 0.f;
#pragma unroll
                for (int g = 0; g < 4; g++) {
                    float2 t = *(float2*)&sm[SRED + g * 2176 + r * 34 + c2];
                    sx += t.x; sy += t.y;
                }
                smU[SOB + r * 68 + h * 32 + c2]     = f2tf(sx);
                smU[SOB + r * 68 + h * 32 + c2 + 1] = f2tf(sy);
            }
        }
        CP_WAIT(0);            // drain pending (h0: G4+G35, h1: G6)
        __syncthreads();       // B4 full: SOB + freshly staged data visible
    }

    // ---- out-proj: out = attn_out @ pw^T + pb (pw raw in SK, cvt at use) ----
    {
        int mtp = w >> 2, nq = w & 3;
        float acc[2][4] = {};
#pragma unroll
        for (int ks = 0; ks < 8; ks++) {
            const unsigned* ab = &smU[SOB + (mtp * 16 + lr) * 68 + ks * 8 + lc];
            unsigned af[4] = {ab[0], ab[8 * 68], ab[4], ab[8 * 68 + 4]};
#pragma unroll
            for (int nt = 0; nt < 2; nt++) {
                const float* bp = &sm[SK + (nq * 16 + nt * 8 + lr) * 68 + ks * 8 + lc];
                unsigned bf[2] = {f2tf(bp[0]), f2tf(bp[4])};
                mma8(acc[nt], af, bf);
            }
        }
#pragma unroll
        for (int nt = 0; nt < 2; nt++) {
            int c0 = nq * 16 + nt * 8 + 2 * lc;
            int r = mtp * 16 + lr;
            float b0 = __ldg(&pb[c0]), b1 = __ldg(&pb[c0 + 1]);
            *(float2*)&out[((size_t)b * NN + n0 + r) * 64 + c0] =
                make_float2(acc[nt][0] + b0, acc[nt][1] + b1);
            *(float2*)&out[((size_t)b * NN + n0 + r + 8) * 64 + c0] =
                make_float2(acc[nt][2] + b0, acc[nt][3] + b1);
        }
    }
}

// ---------------- launch ----------------
extern "C" void kernel_launch(void* const* d_in, const int* in_sizes, int n_in,
                              void* d_out, int out_size) {
    const float* x     = (const float*)d_in[0];
    const float* pos   = (const float*)d_in[1];
    const float* qw    = (const float*)d_in[2];
    const float* qb    = (const float*)d_in[3];
    const float* kvw   = (const float*)d_in[4];
    const float* kvb   = (const float*)d_in[5];
    const float* pw    = (const float*)d_in[6];
    const float* pb    = (const float*)d_in[7];
    const float* srw   = (const float*)d_in[8];
    const float* srb   = (const float*)d_in[9];
    const float* lng   = (const float*)d_in[10];
    const float* lnb   = (const float*)d_in[11];
    const float* alpha = (const float*)d_in[12];
    float* out = (float*)d_out;

    cudaFuncSetAttribute(k_attn, cudaFuncAttributeMaxDynamicSharedMemorySize,
                         SMFW * 4);

    k_transpose<<<256, 256>>>(srw);
    k_conv<<<dim3(16, 32), 256>>>(x);
    k_lnkv<<<512, 256>>>(srb, lng, lnb, kvw, kvb);
    k_attn<<<dim3(256, 4), 512, SMFW * 4>>>(x, pos, qw, qb, pw, pb, alpha, out);
}

// round 15
// speedup vs baseline: 1.0934x; 1.0184x over previous
#include <cuda_runtime.h>
#include <cuda_fp16.h>
#include <math.h>

// Problem constants
#define BB   4
#define NN   16384
#define QK_SCALE 0.17677669529663687f   // 32^-0.5

// ---------------- scratch (device globals; no allocation) ----------------
__device__ float    g_wt[64 * 4096];         // conv weights transposed [o][k]
__device__ float    g_part[32 * 1024 * 64];  // conv split-K partials (32 splits)
__device__ unsigned g_ktf[8 * 256 * 32];     // K tf32 [b*2+h][m][d]
__device__ unsigned g_vhi[8 * 128 * 32];     // V fp16-hi pairs [b*2+h][k2][n]
__device__ unsigned g_vlo[8 * 128 * 32];     // V fp16-lo pairs [b*2+h][k2][n]

// ---------------- helpers ----------------
__device__ __forceinline__ unsigned f2tf(float f) {
    unsigned u; asm("cvt.rna.tf32.f32 %0, %1;" : "=r"(u) : "f"(f)); return u;
}
__device__ __forceinline__ unsigned packhf(float lo, float hi) {
    __half2 h = __floats2half2_rn(lo, hi);      // lo -> lower half, hi -> upper half
    return *(unsigned*)&h;
}
__device__ __forceinline__ float2 unpackhf(unsigned u) {
    __half2 h = *(__half2*)&u;
    return __half22float2(h);                   // x = lower, y = upper
}
__device__ __forceinline__ void mma8(float d[4], const unsigned a[4], const unsigned b[2]) {
    asm volatile(
        "mma.sync.aligned.m16n8k8.row.col.f32.tf32.tf32.f32 "
        "{%0,%1,%2,%3},{%4,%5,%6,%7},{%8,%9},{%0,%1,%2,%3};"
        : "+f"(d[0]), "+f"(d[1]), "+f"(d[2]), "+f"(d[3])
        : "r"(a[0]), "r"(a[1]), "r"(a[2]), "r"(a[3]), "r"(b[0]), "r"(b[1]));
}
__device__ __forceinline__ void mma16h(float d[4], const unsigned a[4], const unsigned b[2]) {
    asm volatile(
        "mma.sync.aligned.m16n8k16.row.col.f32.f16.f16.f32 "
        "{%0,%1,%2,%3},{%4,%5,%6,%7},{%8,%9},{%0,%1,%2,%3};"
        : "+f"(d[0]), "+f"(d[1]), "+f"(d[2]), "+f"(d[3])
        : "r"(a[0]), "r"(a[1]), "r"(a[2]), "r"(a[3]), "r"(b[0]), "r"(b[1]));
}
__device__ __forceinline__ void cpa16(unsigned dst, const void* src) {
    asm volatile("cp.async.cg.shared.global [%0], [%1], 16;" :: "r"(dst), "l"(src));
}
#define CP_COMMIT() asm volatile("cp.async.commit_group;")
#define CP_WAIT(n)  asm volatile("cp.async.wait_group %0;" :: "n"(n))
#define GROUP_BAR(id) asm volatile("bar.sync %0, 128;" :: "r"(id) : "memory")

// ---------------- kernel 0: weight transpose ----------------
__global__ void __launch_bounds__(256) k_transpose(const float* __restrict__ srw) {
    int base = blockIdx.x * 256 + threadIdx.x;
#pragma unroll
    for (int it = 0; it < 4; it++) {
        int i = base + it * 65536;
        int o   = i >> 12;
        int kg  = i & 4095;
        int tap = kg >> 6, c = kg & 63;
        int kh = tap >> 3, kw = tap & 7;
        g_wt[i] = srw[((o * 64 + c) * 8 + kh) * 8 + kw];
    }
}

// ---------------- kernel 1: SR conv, split-K 32, cp.async double-buffered tf32 mma ----
__global__ void __launch_bounds__(256) k_conv(const float* __restrict__ x) {
    __shared__ float As[2][1280];   // [stage][64*20] raw fp32
    __shared__ float Bsm[2][1280];
    unsigned smbA = (unsigned)__cvta_generic_to_shared(&As[0][0]);
    unsigned smbB = (unsigned)__cvta_generic_to_shared(&Bsm[0][0]);
    int tid = threadIdx.x, w = tid >> 5, ln = tid & 31;
    int lr = ln >> 2, lc = ln & 3;
    int mtile = blockIdx.x, ks = blockIdx.y;
    int mt = w & 3, nq = w >> 2;
    float acc[4][4] = {};

    int lm = tid >> 2, lkq = tid & 3;
    int gm = mtile * 64 + lm;
    int bb = gm >> 8, pos = gm & 255;
    int oh = pos >> 4, ow = pos & 15;

    // prefetch iteration 0
    {
        int kg = ks * 128 + lkq * 4;
        int tap = kg >> 6, c = kg & 63;
        int kh = tap >> 3, kw = tap & 7;
        int pix = (oh * 8 + kh) * 128 + (ow * 8 + kw);
        cpa16(smbA + (lm * 20 + lkq * 4) * 4, &x[(bb * NN + pix) * 64 + c]);
        cpa16(smbB + (lm * 20 + lkq * 4) * 4, &g_wt[lm * 4096 + ks * 128 + lkq * 4]);
        CP_COMMIT();
    }

    for (int i = 0; i < 8; i++) {
        if (i < 7) {
            int s = (i + 1) & 1;
            int kg = ks * 128 + (i + 1) * 16 + lkq * 4;
            int tap = kg >> 6, c = kg & 63;
            int kh = tap >> 3, kw = tap & 7;
            int pix = (oh * 8 + kh) * 128 + (ow * 8 + kw);
            cpa16(smbA + (s * 1280 + lm * 20 + lkq * 4) * 4, &x[(bb * NN + pix) * 64 + c]);
            cpa16(smbB + (s * 1280 + lm * 20 + lkq * 4) * 4,
                  &g_wt[lm * 4096 + ks * 128 + (i + 1) * 16 + lkq * 4]);
            CP_COMMIT();
            CP_WAIT(1);
        } else {
            CP_WAIT(0);
        }
        __syncthreads();
        const float* Ab = As[i & 1];
        const float* Bb = Bsm[i & 1];
#pragma unroll
        for (int kb = 0; kb < 16; kb += 8) {
            const float* ap = &Ab[(mt * 16 + lr) * 20 + kb + lc];
            unsigned af[4] = {f2tf(ap[0]), f2tf(ap[8 * 20]), f2tf(ap[4]), f2tf(ap[8 * 20 + 4])};
#pragma unroll
            for (int nt = 0; nt < 4; nt++) {
                const float* bp = &Bb[(nq * 32 + nt * 8 + lr) * 20 + kb + lc];
                unsigned bf[2] = {f2tf(bp[0]), f2tf(bp[4])};
                mma8(acc[nt], af, bf);
            }
        }
        __syncthreads();
    }
    float* outp = &g_part[ks * 65536 + (mtile * 64) * 64];
#pragma unroll
    for (int nt = 0; nt < 4; nt++) {
        int r = mt * 16 + lr, c0 = nq * 32 + nt * 8 + 2 * lc;
        *(float2*)&outp[r * 64 + c0]       = make_float2(acc[nt][0], acc[nt][1]);
        *(float2*)&outp[(r + 8) * 64 + c0] = make_float2(acc[nt][2], acc[nt][3]);
    }
}

// ---------------- kernel 2: reduce partials -> LN -> kv proj -> precomputed formats ----
__global__ void __launch_bounds__(256) k_lnkv(
    const float* __restrict__ srb, const float* __restrict__ lng,
    const float* __restrict__ lnb, const float* __restrict__ kvw,
    const float* __restrict__ kvb)
{
    __shared__ float snx[2][64];
    __shared__ float red[2][2][2];
    __shared__ float vsm[2][64];
    int tid = threadIdx.x, sub = tid >> 7, t = tid & 127;
    int m = blockIdx.x * 2 + sub;
    float v = 0.f;
    if (t < 64) {
        v = srb[t];
#pragma unroll
        for (int s = 0; s < 32; s++) v += g_part[s * 65536 + m * 64 + t];
        float sv = v, sq = v * v;
#pragma unroll
        for (int off = 16; off; off >>= 1) {
            sv += __shfl_xor_sync(0xffffffffu, sv, off);
            sq += __shfl_xor_sync(0xffffffffu, sq, off);
        }
        if ((t & 31) == 0) { red[sub][t >> 5][0] = sv; red[sub][t >> 5][1] = sq; }
    }
    __syncthreads();
    float mu  = (red[sub][0][0] + red[sub][1][0]) * (1.f / 64.f);
    float var = (red[sub][0][1] + red[sub][1][1]) * (1.f / 64.f) - mu * mu;
    float rstd = rsqrtf(var + 1e-5f);
    if (t < 64) snx[sub][t] = (v - mu) * rstd * lng[t] + lnb[t];
    __syncthreads();

    int o = t;
    float acc = kvb[o];
#pragma unroll
    for (int c4 = 0; c4 < 16; c4++) {
        float4 ww = *(const float4*)&kvw[o * 64 + c4 * 4];
        acc += snx[sub][c4 * 4 + 0] * ww.x + snx[sub][c4 * 4 + 1] * ww.y
             + snx[sub][c4 * 4 + 2] * ww.z + snx[sub][c4 * 4 + 3] * ww.w;
    }
    int bb = m >> 8, mm = m & 255;
    if (o < 64) {
        int h = o >> 5, d = o & 31;
        g_ktf[((bb * 2 + h) * 256 + mm) * 32 + d] = f2tf(acc);
    } else {
        vsm[sub][o - 64] = acc;
    }
    __syncthreads();
    if (tid < 64) {
        int h = tid >> 5, d = tid & 31;
        float v0 = vsm[0][tid], v1 = vsm[1][tid];
        unsigned hi = packhf(v0, v1);
        float2 hf = unpackhf(hi);
        unsigned lo = packhf(v0 - hf.x, v1 - hf.y);
        int bb2 = blockIdx.x >> 7, k2 = blockIdx.x & 127;
        int idx = ((bb2 * 2 + h) * 128 + k2) * 32 + d;
        g_vhi[idx] = hi;
        g_vlo[idx] = lo;
    }
}

// ---------------- kernel 3: fused attention (fp16 attn@V, 2-mma) ----------
// smem layout (4-byte words):
#define SQ    0        // q tf32 [r*68 + h*32+d], scale folded          (4352)
#define SOB   4352     // qw raw at start; attn-out tf32 [r*68+c]       (4352)
#define SK    8704     // K tf32 head [m*36+d]; pw raw [o*68+c] at end  (9216)
#define SVH   17920    // V fp16-hi packed [k2*40 + n]                  (5120)
#define SVL   23040    // V fp16-lo packed [k2*40 + n]                  (5120)
#define SRED  28160    // x-tile raw at start; attn@V partials [nh][64][34] (8704)
#define SROW  36864    // row sums [64][4]                              (256)
#define SPOS  37120    // pos tile f32 [64][260]                        (16640)
#define SMFW  53760    // words -> 215040 bytes

__global__ void __launch_bounds__(512, 1) k_attn(
    const float* __restrict__ x,  const float* __restrict__ pos,
    const float* __restrict__ qw, const float* __restrict__ qb,
    const float* __restrict__ pw, const float* __restrict__ pb,
    const float* __restrict__ alpha, float* __restrict__ out)
{
    extern __shared__ float sm[];
    unsigned* smU = (unsigned*)sm;
    unsigned smb = (unsigned)__cvta_generic_to_shared(sm);
    int tid = threadIdx.x, w = tid >> 5, ln = tid & 31;
    int lr = ln >> 2, lc = ln & 3;
    int b = blockIdx.y;
    int n0 = blockIdx.x * 64;
    float a_ = __ldg(alpha);

    int mt = w & 3, nh = w >> 2;            // logits/attn decomposition
    int rowA = mt * 16 + lr;

    // ---- G0: x tile raw -> SRED, qw raw -> SOB ----
#pragma unroll
    for (int it = 0; it < 2; it++) {
        int lin = it * 512 + tid;
        int r = lin >> 4, c4 = (lin & 15) * 4;
        cpa16(smb + (SRED + r * 68 + c4) * 4, &x[((size_t)b * NN + n0 + r) * 64 + c4]);
        cpa16(smb + (SOB + r * 68 + c4) * 4, &qw[r * 64 + c4]);
    }
    CP_COMMIT();
    // ---- G1: K0 + V0 ----
    {
        int b2h = b * 2;
#pragma unroll
        for (int it = 0; it < 4; it++) {
            int lin = it * 512 + tid;
            int m = lin >> 3, d4 = (lin & 7) * 4;
            cpa16(smb + (SK + m * 36 + d4) * 4, &g_ktf[(b2h * 256 + m) * 32 + d4]);
        }
#pragma unroll
        for (int it = 0; it < 2; it++) {
            int lin = it * 512 + tid;
            int k2 = lin >> 3, n4 = (lin & 7) * 4;
            cpa16(smb + (SVH + k2 * 40 + n4) * 4, &g_vhi[(b2h * 128 + k2) * 32 + n4]);
            cpa16(smb + (SVL + k2 * 40 + n4) * 4, &g_vlo[(b2h * 128 + k2) * 32 + n4]);
        }
        CP_COMMIT();
    }
    // ---- G2: pos0 slice (warp-private 16x64) ----
    {
        int b2h = b * 2;
#pragma unroll
        for (int i = 0; i < 8; i++) {
            int q = ln + 32 * i;
            int r = q >> 4, ch = q & 15;
            cpa16(smb + (SPOS + (mt * 16 + r) * 260 + nh * 64 + ch * 4) * 4,
                  &pos[((size_t)b2h * NN + n0 + mt * 16 + r) * 256 + nh * 64 + ch * 4]);
        }
        CP_COMMIT();
    }

    CP_WAIT(2);          // G0 complete (G1,G2 pending)
    __syncthreads();     // B1

    // ---- q-proj: SQ = x @ qw^T (cvt at use, scale folded) ----
    {
        int mtp = w >> 2, nq = w & 3;
        float acc[2][4] = {};
#pragma unroll
        for (int ks = 0; ks < 8; ks++) {
            const float* ap = &sm[SRED + (mtp * 16 + lr) * 68 + ks * 8 + lc];
            unsigned af[4] = {f2tf(ap[0]), f2tf(ap[8 * 68]), f2tf(ap[4]), f2tf(ap[8 * 68 + 4])};
#pragma unroll
            for (int nt = 0; nt < 2; nt++) {
                const float* bp = &sm[SOB + (nq * 16 + nt * 8 + lr) * 68 + ks * 8 + lc];
                unsigned bf[2] = {f2tf(bp[0]), f2tf(bp[4])};
                mma8(acc[nt], af, bf);
            }
        }
#pragma unroll
        for (int nt = 0; nt < 2; nt++) {
            int c0 = nq * 16 + nt * 8 + 2 * lc;
            int r = mtp * 16 + lr;
            float b0 = __ldg(&qb[c0]), b1 = __ldg(&qb[c0 + 1]);
            smU[SQ + r * 68 + c0]           = f2tf((acc[nt][0] + b0) * QK_SCALE);
            smU[SQ + r * 68 + c0 + 1]       = f2tf((acc[nt][1] + b1) * QK_SCALE);
            smU[SQ + (r + 8) * 68 + c0]     = f2tf((acc[nt][2] + b0) * QK_SCALE);
            smU[SQ + (r + 8) * 68 + c0 + 1] = f2tf((acc[nt][3] + b1) * QK_SCALE);
        }
    }
    CP_WAIT(1);          // G1 (K0/V0) complete (G2 pending)
    __syncthreads();     // B2

    for (int h = 0; h < 2; h++) {
        int b2h = b * 2 + h;

        // ---- logits rows [mt*16..+15], cols [nh*64..+63] (registers) ----
        float acc[8][4];
#pragma unroll
        for (int i = 0; i < 8; i++)
            acc[i][0] = acc[i][1] = acc[i][2] = acc[i][3] = 0.f;
#pragma unroll
        for (int ks = 0; ks < 4; ks++) {
            const unsigned* ab = &smU[SQ + rowA * 68 + h * 32 + ks * 8 + lc];
            unsigned af[4] = {ab[0], ab[8 * 68], ab[4], ab[8 * 68 + 4]};
#pragma unroll
            for (int nt = 0; nt < 8; nt++) {
                const unsigned* bp = &smU[SK + (nh * 64 + nt * 8 + lr) * 36 + ks * 8 + lc];
                unsigned bf[2] = {bp[0], bp[4]};
                mma8(acc[nt], af, bf);
            }
        }

        // ---- exp + row sums; exchange within mt-group only ----
        float s0 = 0.f, s1 = 0.f;
#pragma unroll
        for (int nt = 0; nt < 8; nt++) {
            acc[nt][0] = __expf(acc[nt][0]); s0 += acc[nt][0];
            acc[nt][1] = __expf(acc[nt][1]); s0 += acc[nt][1];
            acc[nt][2] = __expf(acc[nt][2]); s1 += acc[nt][2];
            acc[nt][3] = __expf(acc[nt][3]); s1 += acc[nt][3];
        }
        s0 += __shfl_xor_sync(0xffffffffu, s0, 1);
        s0 += __shfl_xor_sync(0xffffffffu, s0, 2);
        s1 += __shfl_xor_sync(0xffffffffu, s1, 1);
        s1 += __shfl_xor_sync(0xffffffffu, s1, 2);
        if (lc == 0) {
            sm[SROW + rowA * 4 + nh]       = s0;
            sm[SROW + (rowA + 8) * 4 + nh] = s1;
        }
        GROUP_BAR(mt + 1);     // only the 4 warps sharing mt need the sums

        float4 s40 = *(float4*)&sm[SROW + rowA * 4];
        float4 s41 = *(float4*)&sm[SROW + (rowA + 8) * 4];
        float inv0 = (1.f - a_) / (s40.x + s40.y + s40.z + s40.w);
        float inv1 = (1.f - a_) / (s41.x + s41.y + s41.z + s41.w);

        if (h == 0) {          // pos0 (G2) — warp-local wait
            CP_WAIT(0);
            __syncwarp();
        }

        // ---- blend (pos from smem) + fp16 pack + attn@V partial (2 mma) ----
        float accO[4][4];
#pragma unroll
        for (int i = 0; i < 4; i++)
            accO[i][0] = accO[i][1] = accO[i][2] = accO[i][3] = 0.f;
#pragma unroll
        for (int kk = 0; kk < 4; kk++) {
            unsigned af[4];
#pragma unroll
            for (int q = 0; q < 2; q++) {
                int nt = 2 * kk + q;
                int cb = nh * 64 + nt * 8 + 2 * lc;
                float2 p0 = *(const float2*)&sm[SPOS + rowA * 260 + cb];
                float2 p1 = *(const float2*)&sm[SPOS + (rowA + 8) * 260 + cb];
                float w00 = acc[nt][0] * inv0 + a_ * p0.x;
                float w01 = acc[nt][1] * inv0 + a_ * p0.y;
                float w10 = acc[nt][2] * inv1 + a_ * p1.x;
                float w11 = acc[nt][3] * inv1 + a_ * p1.y;
                af[2 * q]     = packhf(w00, w01);
                af[2 * q + 1] = packhf(w10, w11);
            }
            int k2b = nh * 32 + kk * 8;
#pragma unroll
            for (int ntv = 0; ntv < 4; ntv++) {
                const unsigned* bph = &smU[SVH + (k2b + lc) * 40 + ntv * 8 + lr];
                const unsigned* bpl = &smU[SVL + (k2b + lc) * 40 + ntv * 8 + lr];
                unsigned bh[2] = {bph[0], bph[4 * 40]};
                unsigned bl[2] = {bpl[0], bpl[4 * 40]};
                mma16h(accO[ntv], af, bh);
                mma16h(accO[ntv], af, bl);
            }
        }

        if (h == 0) {          // G4: pos1 slice (own slice read done; warp-private)
#pragma unroll
            for (int i = 0; i < 8; i++) {
                int q = ln + 32 * i;
                int r = q >> 4, ch = q & 15;
                cpa16(smb + (SPOS + (mt * 16 + r) * 260 + nh * 64 + ch * 4) * 4,
                      &pos[((size_t)(b2h + 1) * NN + n0 + mt * 16 + r) * 256 + nh * 64 + ch * 4]);
            }
            CP_COMMIT();
        }

        // write partials [nh][row][col]
#pragma unroll
        for (int ntv = 0; ntv < 4; ntv++) {
            int cc = ntv * 8 + 2 * lc;
            *(float2*)&sm[SRED + nh * 2176 + rowA * 34 + cc] =
                make_float2(accO[ntv][0], accO[ntv][1]);
            *(float2*)&sm[SRED + nh * 2176 + (rowA + 8) * 34 + cc] =
                make_float2(accO[ntv][2], accO[ntv][3]);
        }
        __syncthreads();       // B3 full: partials visible; all SK/SV reads done

        if (h == 0) {          // G35: K1 + V1 (after ALL logits/attn@V reads)
#pragma unroll
            for (int it = 0; it < 4; it++) {
                int lin = it * 512 + tid;
                int m = lin >> 3, d4 = (lin & 7) * 4;
                cpa16(smb + (SK + m * 36 + d4) * 4,
                      &g_ktf[((b2h + 1) * 256 + m) * 32 + d4]);
            }
#pragma unroll
            for (int it = 0; it < 2; it++) {
                int lin = it * 512 + tid;
                int k2 = lin >> 3, n4 = (lin & 7) * 4;
                cpa16(smb + (SVH + k2 * 40 + n4) * 4,
                      &g_vhi[((b2h + 1) * 128 + k2) * 32 + n4]);
                cpa16(smb + (SVL + k2 * 40 + n4) * 4,
                      &g_vlo[((b2h + 1) * 128 + k2) * 32 + n4]);
            }
            CP_COMMIT();
        } else {               // G6: pw raw -> SK (K reads all done)
#pragma unroll
            for (int it = 0; it < 2; it++) {
                int lin = it * 512 + tid;
                int r = lin >> 4, c4 = (lin & 15) * 4;
                cpa16(smb + (SK + r * 68 + c4) * 4, &pw[r * 64 + c4]);
            }
            CP_COMMIT();
        }

        // ---- reduce own-group rows: partials -> SOB (tf32) ----
        {
            int tg = (w >> 2) * 32 + ln;      // 0..127 within mt-group
#pragma unroll
            for (int i = 0; i < 2; i++) {
                int p = i * 128 + tg;         // 0..255
                int r = mt * 16 + (p >> 4);
                int c2 = (p & 15) * 2;
                float sx = 0.f, sy = 0.f;
#pragma unroll
                for (int g = 0; g < 4; g++) {
                    float2 t = *(float2*)&sm[SRED + g * 2176 + r * 34 + c2];
                    sx += t.x; sy += t.y;
                }
                smU[SOB + r * 68 + h * 32 + c2]     = f2tf(sx);
                smU[SOB + r * 68 + h * 32 + c2 + 1] = f2tf(sy);
            }
        }
        CP_WAIT(0);            // drain pending (h0: G4+G35, h1: G6)
        __syncthreads();       // B4 full: SOB + freshly staged data visible
    }

    // ---- out-proj: out = attn_out @ pw^T + pb (pw raw in SK, cvt at use) ----
    {
        int mtp = w >> 2, nq = w & 3;
        float acc[2][4] = {};
#pragma unroll
        for (int ks = 0; ks < 8; ks++) {
            const unsigned* ab = &smU[SOB + (mtp * 16 + lr) * 68 + ks * 8 + lc];
            unsigned af[4] = {ab[0], ab[8 * 68], ab[4], ab[8 * 68 + 4]};
#pragma unroll
            for (int nt = 0; nt < 2; nt++) {
                const float* bp = &sm[SK + (nq * 16 + nt * 8 + lr) * 68 + ks * 8 + lc];
                unsigned bf[2] = {f2tf(bp[0]), f2tf(bp[4])};
                mma8(acc[nt], af, bf);
            }
        }
#pragma unroll
        for (int nt = 0; nt < 2; nt++) {
            int c0 = nq * 16 + nt * 8 + 2 * lc;
            int r = mtp * 16 + lr;
            float b0 = __ldg(&pb[c0]), b1 = __ldg(&pb[c0 + 1]);
            *(float2*)&out[((size_t)b * NN + n0 + r) * 64 + c0] =
                make_float2(acc[nt][0] + b0, acc[nt][1] + b1);
            *(float2*)&out[((size_t)b * NN + n0 + r + 8) * 64 + c0] =
                make_float2(acc[nt][2] + b0, acc[nt][3] + b1);
        }
    }
}

// ---------------- launch ----------------
extern "C" void kernel_launch(void* const* d_in, const int* in_sizes, int n_in,
                              void* d_out, int out_size) {
    const float* x     = (const float*)d_in[0];
    const float* pos   = (const float*)d_in[1];
    const float* qw    = (const float*)d_in[2];
    const float* qb    = (const float*)d_in[3];
    const float* kvw   = (const float*)d_in[4];
    const float* kvb   = (const float*)d_in[5];
    const float* pw    = (const float*)d_in[6];
    const float* pb    = (const float*)d_in[7];
    const float* srw   = (const float*)d_in[8];
    const float* srb   = (const float*)d_in[9];
    const float* lng   = (const float*)d_in[10];
    const float* lnb   = (const float*)d_in[11];
    const float* alpha = (const float*)d_in[12];
    float* out = (float*)d_out;

    cudaFuncSetAttribute(k_attn, cudaFuncAttributeMaxDynamicSharedMemorySize,
                         SMFW * 4);

    k_transpose<<<256, 256>>>(srw);
    k_conv<<<dim3(16, 32), 256>>>(x);
    k_lnkv<<<512, 256>>>(srb, lng, lnb, kvw, kvb);
    k_attn<<<dim3(256, 4), 512, SMFW * 4>>>(x, pos, qw, qb, pw, pb, alpha, out);
}

// round 17
// speedup vs baseline: 1.1938x; 1.0918x over previous
#include <cuda_runtime.h>
#include <cuda_fp16.h>
#include <math.h>

// Problem constants
#define BB   4
#define NN   16384
#define QK_SCALE 0.17677669529663687f   // 32^-0.5

// ---------------- scratch (device globals; no allocation) ----------------
__device__ float    g_wt[64 * 4096];         // conv weights transposed [o][k]
__device__ float    g_part[32 * 1024 * 64];  // conv split-K partials (32 splits)
__device__ unsigned g_khf[8 * 256 * 16];     // K fp16 pairs [b*2+h][m][d2]
__device__ unsigned g_vhi[8 * 128 * 32];     // V fp16-hi pairs [b*2+h][k2][n]
__device__ unsigned g_vlo[8 * 128 * 32];     // V fp16-lo pairs [b*2+h][k2][n]

// ---------------- helpers ----------------
__device__ __forceinline__ unsigned f2tf(float f) {
    unsigned u; asm("cvt.rna.tf32.f32 %0, %1;" : "=r"(u) : "f"(f)); return u;
}
__device__ __forceinline__ unsigned packhf(float lo, float hi) {
    __half2 h = __floats2half2_rn(lo, hi);      // lo -> lower half, hi -> upper half
    return *(unsigned*)&h;
}
__device__ __forceinline__ float2 unpackhf(unsigned u) {
    __half2 h = *(__half2*)&u;
    return __half22float2(h);
}
__device__ __forceinline__ void mma8(float d[4], const unsigned a[4], const unsigned b[2]) {
    asm volatile(
        "mma.sync.aligned.m16n8k8.row.col.f32.tf32.tf32.f32 "
        "{%0,%1,%2,%3},{%4,%5,%6,%7},{%8,%9},{%0,%1,%2,%3};"
        : "+f"(d[0]), "+f"(d[1]), "+f"(d[2]), "+f"(d[3])
        : "r"(a[0]), "r"(a[1]), "r"(a[2]), "r"(a[3]), "r"(b[0]), "r"(b[1]));
}
__device__ __forceinline__ void mma16h(float d[4], const unsigned a[4], const unsigned b[2]) {
    asm volatile(
        "mma.sync.aligned.m16n8k16.row.col.f32.f16.f16.f32 "
        "{%0,%1,%2,%3},{%4,%5,%6,%7},{%8,%9},{%0,%1,%2,%3};"
        : "+f"(d[0]), "+f"(d[1]), "+f"(d[2]), "+f"(d[3])
        : "r"(a[0]), "r"(a[1]), "r"(a[2]), "r"(a[3]), "r"(b[0]), "r"(b[1]));
}
__device__ __forceinline__ void cpa16(unsigned dst, const void* src) {
    asm volatile("cp.async.cg.shared.global [%0], [%1], 16;" :: "r"(dst), "l"(src));
}
#define CP_COMMIT() asm volatile("cp.async.commit_group;")
#define CP_WAIT(n)  asm volatile("cp.async.wait_group %0;" :: "n"(n))
#define GROUP_BAR(id) asm volatile("bar.sync %0, 128;" :: "r"(id) : "memory")

// ---------------- kernel 0: weight transpose ----------------
__global__ void __launch_bounds__(256) k_transpose(const float* __restrict__ srw) {
    int base = blockIdx.x * 256 + threadIdx.x;
#pragma unroll
    for (int it = 0; it < 4; it++) {
        int i = base + it * 65536;
        int o   = i >> 12;
        int kg  = i & 4095;
        int tap = kg >> 6, c = kg & 63;
        int kh = tap >> 3, kw = tap & 7;
        g_wt[i] = srw[((o * 64 + c) * 8 + kh) * 8 + kw];
    }
}

// ---------------- kernel 1: SR conv, split-K 32, cp.async double-buffered tf32 mma ----
__global__ void __launch_bounds__(256) k_conv(const float* __restrict__ x) {
    __shared__ float As[2][1280];
    __shared__ float Bsm[2][1280];
    unsigned smbA = (unsigned)__cvta_generic_to_shared(&As[0][0]);
    unsigned smbB = (unsigned)__cvta_generic_to_shared(&Bsm[0][0]);
    int tid = threadIdx.x, w = tid >> 5, ln = tid & 31;
    int lr = ln >> 2, lc = ln & 3;
    int mtile = blockIdx.x, ks = blockIdx.y;
    int mt = w & 3, nq = w >> 2;
    float acc[4][4] = {};

    int lm = tid >> 2, lkq = tid & 3;
    int gm = mtile * 64 + lm;
    int bb = gm >> 8, pos = gm & 255;
    int oh = pos >> 4, ow = pos & 15;

    {
        int kg = ks * 128 + lkq * 4;
        int tap = kg >> 6, c = kg & 63;
        int kh = tap >> 3, kw = tap & 7;
        int pix = (oh * 8 + kh) * 128 + (ow * 8 + kw);
        cpa16(smbA + (lm * 20 + lkq * 4) * 4, &x[(bb * NN + pix) * 64 + c]);
        cpa16(smbB + (lm * 20 + lkq * 4) * 4, &g_wt[lm * 4096 + ks * 128 + lkq * 4]);
        CP_COMMIT();
    }

    for (int i = 0; i < 8; i++) {
        if (i < 7) {
            int s = (i + 1) & 1;
            int kg = ks * 128 + (i + 1) * 16 + lkq * 4;
            int tap = kg >> 6, c = kg & 63;
            int kh = tap >> 3, kw = tap & 7;
            int pix = (oh * 8 + kh) * 128 + (ow * 8 + kw);
            cpa16(smbA + (s * 1280 + lm * 20 + lkq * 4) * 4, &x[(bb * NN + pix) * 64 + c]);
            cpa16(smbB + (s * 1280 + lm * 20 + lkq * 4) * 4,
                  &g_wt[lm * 4096 + ks * 128 + (i + 1) * 16 + lkq * 4]);
            CP_COMMIT();
            CP_WAIT(1);
        } else {
            CP_WAIT(0);
        }
        __syncthreads();
        const float* Ab = As[i & 1];
        const float* Bb = Bsm[i & 1];
#pragma unroll
        for (int kb = 0; kb < 16; kb += 8) {
            const float* ap = &Ab[(mt * 16 + lr) * 20 + kb + lc];
            unsigned af[4] = {f2tf(ap[0]), f2tf(ap[8 * 20]), f2tf(ap[4]), f2tf(ap[8 * 20 + 4])};
#pragma unroll
            for (int nt = 0; nt < 4; nt++) {
                const float* bp = &Bb[(nq * 32 + nt * 8 + lr) * 20 + kb + lc];
                unsigned bf[2] = {f2tf(bp[0]), f2tf(bp[4])};
                mma8(acc[nt], af, bf);
            }
        }
        __syncthreads();
    }
    float* outp = &g_part[ks * 65536 + (mtile * 64) * 64];
#pragma unroll
    for (int nt = 0; nt < 4; nt++) {
        int r = mt * 16 + lr, c0 = nq * 32 + nt * 8 + 2 * lc;
        *(float2*)&outp[r * 64 + c0]       = make_float2(acc[nt][0], acc[nt][1]);
        *(float2*)&outp[(r + 8) * 64 + c0] = make_float2(acc[nt][2], acc[nt][3]);
    }
}

// ---------------- kernel 2: reduce partials -> LN -> kv proj -> precomputed formats ----
__global__ void __launch_bounds__(256) k_lnkv(
    const float* __restrict__ srb, const float* __restrict__ lng,
    const float* __restrict__ lnb, const float* __restrict__ kvw,
    const float* __restrict__ kvb)
{
    __shared__ float snx[2][64];
    __shared__ float red[2][2][2];
    __shared__ float vsm[2][64];
    int tid = threadIdx.x, sub = tid >> 7, t = tid & 127;
    int m = blockIdx.x * 2 + sub;
    float v = 0.f;
    if (t < 64) {
        v = srb[t];
#pragma unroll
        for (int s = 0; s < 32; s++) v += g_part[s * 65536 + m * 64 + t];
        float sv = v, sq = v * v;
#pragma unroll
        for (int off = 16; off; off >>= 1) {
            sv += __shfl_xor_sync(0xffffffffu, sv, off);
            sq += __shfl_xor_sync(0xffffffffu, sq, off);
        }
        if ((t & 31) == 0) { red[sub][t >> 5][0] = sv; red[sub][t >> 5][1] = sq; }
    }
    __syncthreads();
    float mu  = (red[sub][0][0] + red[sub][1][0]) * (1.f / 64.f);
    float var = (red[sub][0][1] + red[sub][1][1]) * (1.f / 64.f) - mu * mu;
    float rstd = rsqrtf(var + 1e-5f);
    if (t < 64) snx[sub][t] = (v - mu) * rstd * lng[t] + lnb[t];
    __syncthreads();

    int o = t;
    float acc = kvb[o];
#pragma unroll
    for (int c4 = 0; c4 < 16; c4++) {
        float4 ww = *(const float4*)&kvw[o * 64 + c4 * 4];
        acc += snx[sub][c4 * 4 + 0] * ww.x + snx[sub][c4 * 4 + 1] * ww.y
             + snx[sub][c4 * 4 + 2] * ww.z + snx[sub][c4 * 4 + 3] * ww.w;
    }
    int bb = m >> 8, mm = m & 255;
    if (o < 64) {            // K -> fp16 packed pairs along d (lane shfl)
        int h = o >> 5, d = o & 31;
        float dnext = __shfl_down_sync(0xffffffffu, acc, 1);
        if ((d & 1) == 0)
            g_khf[((bb * 2 + h) * 256 + mm) * 16 + (d >> 1)] = packhf(acc, dnext);
    } else {
        vsm[sub][o - 64] = acc;
    }
    __syncthreads();
    if (tid < 64) {
        int h = tid >> 5, d = tid & 31;
        float v0 = vsm[0][tid], v1 = vsm[1][tid];
        unsigned hi = packhf(v0, v1);
        float2 hf = unpackhf(hi);
        unsigned lo = packhf(v0 - hf.x, v1 - hf.y);
        int bb2 = blockIdx.x >> 7, k2 = blockIdx.x & 127;
        int idx = ((bb2 * 2 + h) * 128 + k2) * 32 + d;
        g_vhi[idx] = hi;
        g_vlo[idx] = lo;
    }
}

// ---------------- kernel 3: fused attention (fp16 QK + fp16 attn@V) ----------
// smem layout (4-byte words):
#define SQ    0        // q fp16 packed [r*36 + o2], scale folded       (2304)
#define SOB   2304     // qw raw at start; attn-out tf32 [r*68+c]       (4352)
#define SK    6656     // K fp16 packed [m*20+d2]; pw raw [o*68+c] end  (5120)
#define SVH   11776    // V fp16-hi packed [k2*40 + n]                  (5120)
#define SVL   16896    // V fp16-lo packed [k2*40 + n]                  (5120)
#define SRED  22016    // x-tile raw at start; attn@V partials [nh][64][34] (8704)
#define SROW  30720    // row sums [64][4]                              (256)
#define SPOS  30976    // pos tile f32 [64][260]                        (16640)
#define SMFW  47616    // words -> 190464 bytes

__global__ void __launch_bounds__(512, 1) k_attn(
    const float* __restrict__ x,  const float* __restrict__ pos,
    const float* __restrict__ qw, const float* __restrict__ qb,
    const float* __restrict__ pw, const float* __restrict__ pb,
    const float* __restrict__ alpha, float* __restrict__ out)
{
    extern __shared__ float sm[];
    unsigned* smU = (unsigned*)sm;
    unsigned smb = (unsigned)__cvta_generic_to_shared(sm);
    int tid = threadIdx.x, w = tid >> 5, ln = tid & 31;
    int lr = ln >> 2, lc = ln & 3;
    int b = blockIdx.y;
    int n0 = blockIdx.x * 64;
    float a_ = __ldg(alpha);

    int mt = w & 3, nh = w >> 2;            // logits/attn decomposition
    int rowA = mt * 16 + lr;

    // ---- G0: x tile raw -> SRED, qw raw -> SOB ----
#pragma unroll
    for (int it = 0; it < 2; it++) {
        int lin = it * 512 + tid;
        int r = lin >> 4, c4 = (lin & 15) * 4;
        cpa16(smb + (SRED + r * 68 + c4) * 4, &x[((size_t)b * NN + n0 + r) * 64 + c4]);
        cpa16(smb + (SOB + r * 68 + c4) * 4, &qw[r * 64 + c4]);
    }
    CP_COMMIT();
    // ---- G1: K0 (fp16) + V0 ----
    {
        int b2h = b * 2;
        {
            int lin = tid;                      // 1024 uint4 over 2 iters
#pragma unroll
            for (int it = 0; it < 2; it++) {
                int l2 = it * 512 + lin;
                int m = l2 >> 2, d4 = (l2 & 3) * 4;
                cpa16(smb + (SK + m * 20 + d4) * 4, &g_khf[(b2h * 256 + m) * 16 + d4]);
            }
        }
#pragma unroll
        for (int it = 0; it < 2; it++) {
            int lin = it * 512 + tid;
            int k2 = lin >> 3, n4 = (lin & 7) * 4;
            cpa16(smb + (SVH + k2 * 40 + n4) * 4, &g_vhi[(b2h * 128 + k2) * 32 + n4]);
            cpa16(smb + (SVL + k2 * 40 + n4) * 4, &g_vlo[(b2h * 128 + k2) * 32 + n4]);
        }
        CP_COMMIT();
    }
    // ---- G2: pos0 slice (warp-private 16x64) ----
    {
        int b2h = b * 2;
#pragma unroll
        for (int i = 0; i < 8; i++) {
            int q = ln + 32 * i;
            int r = q >> 4, ch = q & 15;
            cpa16(smb + (SPOS + (mt * 16 + r) * 260 + nh * 64 + ch * 4) * 4,
                  &pos[((size_t)b2h * NN + n0 + mt * 16 + r) * 256 + nh * 64 + ch * 4]);
        }
        CP_COMMIT();
    }

    CP_WAIT(2);          // G0 complete
    __syncthreads();     // B1

    // ---- q-proj: SQ = x @ qw^T (tf32 math, fp16 packed store, scale folded) ----
    {
        int mtp = w >> 2, nq = w & 3;
        float acc[2][4] = {};
#pragma unroll
        for (int ks = 0; ks < 8; ks++) {
            const float* ap = &sm[SRED + (mtp * 16 + lr) * 68 + ks * 8 + lc];
            unsigned af[4] = {f2tf(ap[0]), f2tf(ap[8 * 68]), f2tf(ap[4]), f2tf(ap[8 * 68 + 4])};
#pragma unroll
            for (int nt = 0; nt < 2; nt++) {
                const float* bp = &sm[SOB + (nq * 16 + nt * 8 + lr) * 68 + ks * 8 + lc];
                unsigned bf[2] = {f2tf(bp[0]), f2tf(bp[4])};
                mma8(acc[nt], af, bf);
            }
        }
#pragma unroll
        for (int nt = 0; nt < 2; nt++) {
            int c0 = nq * 16 + nt * 8 + 2 * lc;
            int r = mtp * 16 + lr;
            float b0 = __ldg(&qb[c0]), b1 = __ldg(&qb[c0 + 1]);
            smU[SQ + r * 36 + (c0 >> 1)] =
                packhf((acc[nt][0] + b0) * QK_SCALE, (acc[nt][1] + b1) * QK_SCALE);
            smU[SQ + (r + 8) * 36 + (c0 >> 1)] =
                packhf((acc[nt][2] + b0) * QK_SCALE, (acc[nt][3] + b1) * QK_SCALE);
        }
    }
    CP_WAIT(1);          // G1 (K0/V0) complete
    __syncthreads();     // B2

    for (int h = 0; h < 2; h++) {
        int b2h = b * 2 + h;

        // ---- logits rows [mt*16..+15], cols [nh*64..+63]: fp16 m16n8k16 ----
        float acc[8][4];
#pragma unroll
        for (int i = 0; i < 8; i++)
            acc[i][0] = acc[i][1] = acc[i][2] = acc[i][3] = 0.f;
#pragma unroll
        for (int ks = 0; ks < 2; ks++) {        // 2 chunks of k=16 (d2 groups of 8)
            const unsigned* aq = &smU[SQ + rowA * 36 + h * 16 + ks * 8 + lc];
            unsigned af[4] = {aq[0], aq[8 * 36], aq[4], aq[8 * 36 + 4]};
#pragma unroll
            for (int nt = 0; nt < 8; nt++) {
                const unsigned* bp = &smU[SK + (nh * 64 + nt * 8 + lr) * 20 + ks * 8 + lc];
                unsigned bf[2] = {bp[0], bp[4]};
                mma16h(acc[nt], af, bf);
            }
        }

        // ---- exp + row sums; exchange within mt-group only ----
        float s0 = 0.f, s1 = 0.f;
#pragma unroll
        for (int nt = 0; nt < 8; nt++) {
            acc[nt][0] = __expf(acc[nt][0]); s0 += acc[nt][0];
            acc[nt][1] = __expf(acc[nt][1]); s0 += acc[nt][1];
            acc[nt][2] = __expf(acc[nt][2]); s1 += acc[nt][2];
            acc[nt][3] = __expf(acc[nt][3]); s1 += acc[nt][3];
        }
        s0 += __shfl_xor_sync(0xffffffffu, s0, 1);
        s0 += __shfl_xor_sync(0xffffffffu, s0, 2);
        s1 += __shfl_xor_sync(0xffffffffu, s1, 1);
        s1 += __shfl_xor_sync(0xffffffffu, s1, 2);
        if (lc == 0) {
            sm[SROW + rowA * 4 + nh]       = s0;
            sm[SROW + (rowA + 8) * 4 + nh] = s1;
        }
        GROUP_BAR(mt + 1);

        float4 s40 = *(float4*)&sm[SROW + rowA * 4];
        float4 s41 = *(float4*)&sm[SROW + (rowA + 8) * 4];
        float inv0 = (1.f - a_) / (s40.x + s40.y + s40.z + s40.w);
        float inv1 = (1.f - a_) / (s41.x + s41.y + s41.z + s41.w);

        if (h == 0) {
            CP_WAIT(0);
            __syncwarp();
        }

        // ---- blend (pos from smem) + fp16 pack + attn@V partial (2 mma) ----
        float accO[4][4];
#pragma unroll
        for (int i = 0; i < 4; i++)
            accO[i][0] = accO[i][1] = accO[i][2] = accO[i][3] = 0.f;
#pragma unroll
        for (int kk = 0; kk < 4; kk++) {
            unsigned af[4];
#pragma unroll
            for (int q = 0; q < 2; q++) {
                int nt = 2 * kk + q;
                int cb = nh * 64 + nt * 8 + 2 * lc;
                float2 p0 = *(const float2*)&sm[SPOS + rowA * 260 + cb];
                float2 p1 = *(const float2*)&sm[SPOS + (rowA + 8) * 260 + cb];
                float w00 = acc[nt][0] * inv0 + a_ * p0.x;
                float w01 = acc[nt][1] * inv0 + a_ * p0.y;
                float w10 = acc[nt][2] * inv1 + a_ * p1.x;
                float w11 = acc[nt][3] * inv1 + a_ * p1.y;
                af[2 * q]     = packhf(w00, w01);
                af[2 * q + 1] = packhf(w10, w11);
            }
            int k2b = nh * 32 + kk * 8;
#pragma unroll
            for (int ntv = 0; ntv < 4; ntv++) {
                const unsigned* bph = &smU[SVH + (k2b + lc) * 40 + ntv * 8 + lr];
                const unsigned* bpl = &smU[SVL + (k2b + lc) * 40 + ntv * 8 + lr];
                unsigned bh[2] = {bph[0], bph[4 * 40]};
                unsigned bl[2] = {bpl[0], bpl[4 * 40]};
                mma16h(accO[ntv], af, bh);
                mma16h(accO[ntv], af, bl);
            }
        }

        if (h == 0) {          // G4: pos1 slice (warp-private)
#pragma unroll
            for (int i = 0; i < 8; i++) {
                int q = ln + 32 * i;
                int r = q >> 4, ch = q & 15;
                cpa16(smb + (SPOS + (mt * 16 + r) * 260 + nh * 64 + ch * 4) * 4,
                      &pos[((size_t)(b2h + 1) * NN + n0 + mt * 16 + r) * 256 + nh * 64 + ch * 4]);
            }
            CP_COMMIT();
        }

        // write partials [nh][row][col]
#pragma unroll
        for (int ntv = 0; ntv < 4; ntv++) {
            int cc = ntv * 8 + 2 * lc;
            *(float2*)&sm[SRED + nh * 2176 + rowA * 34 + cc] =
                make_float2(accO[ntv][0], accO[ntv][1]);
            *(float2*)&sm[SRED + nh * 2176 + (rowA + 8) * 34 + cc] =
                make_float2(accO[ntv][2], accO[ntv][3]);
        }
        __syncthreads();       // B3: partials visible; all SK/SV reads done

        if (h == 0) {          // G35: K1 (fp16) + V1
#pragma unroll
            for (int it = 0; it < 2; it++) {
                int l2 = it * 512 + tid;
                int m = l2 >> 2, d4 = (l2 & 3) * 4;
                cpa16(smb + (SK + m * 20 + d4) * 4,
                      &g_khf[((b2h + 1) * 256 + m) * 16 + d4]);
            }
#pragma unroll
            for (int it = 0; it < 2; it++) {
                int lin = it * 512 + tid;
                int k2 = lin >> 3, n4 = (lin & 7) * 4;
                cpa16(smb + (SVH + k2 * 40 + n4) * 4,
                      &g_vhi[((b2h + 1) * 128 + k2) * 32 + n4]);
                cpa16(smb + (SVL + k2 * 40 + n4) * 4,
                      &g_vlo[((b2h + 1) * 128 + k2) * 32 + n4]);
            }
            CP_COMMIT();
        } else {               // G6: pw raw -> SK (K reads all done)
#pragma unroll
            for (int it = 0; it < 2; it++) {
                int lin = it * 512 + tid;
                int r = lin >> 4, c4 = (lin & 15) * 4;
                cpa16(smb + (SK + r * 68 + c4) * 4, &pw[r * 64 + c4]);
            }
            CP_COMMIT();
        }

        // ---- reduce own-group rows: partials -> SOB (tf32) ----
        {
            int tg = (w >> 2) * 32 + ln;
#pragma unroll
            for (int i = 0; i < 2; i++) {
                int p = i * 128 + tg;
                int r = mt * 16 + (p >> 4);
                int c2 = (p & 15) * 2;
                float sx = 0.f, sy = 0.f;
#pragma unroll
                for (int g = 0; g < 4; g++) {
                    float2 t = *(float2*)&sm[SRED + g * 2176 + r * 34 + c2];
                    sx += t.x; sy += t.y;
                }
                smU[SOB + r * 68 + h * 32 + c2]     = f2tf(sx);
                smU[SOB + r * 68 + h * 32 + c2 + 1] = f2tf(sy);
            }
        }
        CP_WAIT(0);
        __syncthreads();       // B4
    }

    // ---- out-proj: out = attn_out @ pw^T + pb (pw raw in SK, cvt at use) ----
    {
        int mtp = w >> 2, nq = w & 3;
        float acc[2][4] = {};
#pragma unroll
        for (int ks = 0; ks < 8; ks++) {
            const unsigned* ab = &smU[SOB + (mtp * 16 + lr) * 68 + ks * 8 + lc];
            unsigned af[4] = {ab[0], ab[8 * 68], ab[4], ab[8 * 68 + 4]};
#pragma unroll
            for (int nt = 0; nt < 2; nt++) {
                const float* bp = &sm[SK + (nq * 16 + nt * 8 + lr) * 68 + ks * 8 + lc];
                unsigned bf[2] = {f2tf(bp[0]), f2tf(bp[4])};
                mma8(acc[nt], af, bf);
            }
        }
#pragma unroll
        for (int nt = 0; nt < 2; nt++) {
            int c0 = nq * 16 + nt * 8 + 2 * lc;
            int r = mtp * 16 + lr;
            float b0 = __ldg(&pb[c0]), b1 = __ldg(&pb[c0 + 1]);
            *(float2*)&out[((size_t)b * NN + n0 + r) * 64 + c0] =
                make_float2(acc[nt][0] + b0, acc[nt][1] + b1);
            *(float2*)&out[((size_t)b * NN + n0 + r + 8) * 64 + c0] =
                make_float2(acc[nt][2] + b0, acc[nt][3] + b1);
        }
    }
}

// ---------------- launch ----------------
extern "C" void kernel_launch(void* const* d_in, const int* in_sizes, int n_in,
                              void* d_out, int out_size) {
    const float* x     = (const float*)d_in[0];
    const float* pos   = (const float*)d_in[1];
    const float* qw    = (const float*)d_in[2];
    const float* qb    = (const float*)d_in[3];
    const float* kvw   = (const float*)d_in[4];
    const float* kvb   = (const float*)d_in[5];
    const float* pw    = (const float*)d_in[6];
    const float* pb    = (const float*)d_in[7];
    const float* srw   = (const float*)d_in[8];
    const float* srb   = (const float*)d_in[9];
    const float* lng   = (const float*)d_in[10];
    const float* lnb   = (const float*)d_in[11];
    const float* alpha = (const float*)d_in[12];
    float* out = (float*)d_out;

    cudaFuncSetAttribute(k_attn, cudaFuncAttributeMaxDynamicSharedMemorySize,
                         SMFW * 4);

    k_transpose<<<256, 256>>>(srw);
    k_conv<<<dim3(16, 32), 256>>>(x);
    k_lnkv<<<512, 256>>>(srb, lng, lnb, kvw, kvb);
    k_attn<<<dim3(256, 4), 512, SMFW * 4>>>(x, pos, qw, qb, pw, pb, alpha, out);
}